// round 8
// baseline (speedup 1.0000x reference)
#include <cuda_runtime.h>

#define NN      100000
#define INC     512
#define HID     256
#define OUTC    128
#define CB      64              // channel block for APPNP
#define NCB     (OUTC / CB)     // 2 blocks
#define EMAX    1600000
#define KSTEPS  10
#define ALPHA_F 0.1f
#define ONEMA_F 0.9f
#define LNEPS   1e-5f

// ---------------- static device scratch (no allocation allowed) ----------------
__device__ float g_h1[(size_t)NN * HID];
__device__ float g_h2[(size_t)NN * HID];
__device__ float g_h0[(size_t)NN * OUTC];     // BLOCKED: [cb][node][64]
__device__ float g_bufA[(size_t)NN * CB];
__device__ float g_bufB[(size_t)NN * CB];
__device__ float g_dis[NN];
__device__ int   g_cnt[NN];
__device__ int   g_fill[NN];
__device__ int   g_rowptr[NN + 1];
__device__ int2  g_csr[EMAX];                 // packed {src, weight-bits}
__device__ int   g_bsum[512];

// ---------------- fp32 SGEMM: C = A@B + bias, reg-prefetch pipeline -------------
// 128x128 tile, 256 threads, 8x8 micro-tile, K-tile 8.
// blocked=1: write C in 64-col-blocked layout: ((n>>6)*M + m)*64 + (n&63)
__global__ void __launch_bounds__(256, 2)
sgemm_bias(const float* __restrict__ A, const float* __restrict__ B,
           const float* __restrict__ bias, float* __restrict__ C,
           int M, int K, int N, int blocked)
{
    __shared__ float sA[8][128];
    __shared__ float sB[8][128];

    const int tid = threadIdx.x;
    const int bm  = blockIdx.y * 128;
    const int bn  = blockIdx.x * 128;
    const int tx  = tid & 15;
    const int ty  = tid >> 4;

    const int a_row = tid >> 1;
    const int a_k4  = (tid & 1) * 4;
    const bool m_ok = (bm + a_row) < M;
    const int b_k = tid >> 5;
    const int b_n = (tid & 31) * 4;

    const float* a_ptr = A + (size_t)(bm + a_row) * K + a_k4;
    const float* b_ptr = B + (size_t)b_k * N + (bn + b_n);

    float acc[8][8] = {};

    float4 avr = m_ok ? *(const float4*)a_ptr : make_float4(0.f, 0.f, 0.f, 0.f);
    float4 bvr = *(const float4*)b_ptr;

    const int nt = K / 8;
    for (int t = 0; t < nt; t++) {
        sA[a_k4 + 0][a_row] = avr.x;
        sA[a_k4 + 1][a_row] = avr.y;
        sA[a_k4 + 2][a_row] = avr.z;
        sA[a_k4 + 3][a_row] = avr.w;
        *(float4*)&sB[b_k][b_n] = bvr;
        __syncthreads();

        if (t + 1 < nt) {
            avr = m_ok ? *(const float4*)(a_ptr + (t + 1) * 8)
                       : make_float4(0.f, 0.f, 0.f, 0.f);
            bvr = *(const float4*)(b_ptr + (size_t)(t + 1) * 8 * N);
        }

        #pragma unroll
        for (int kk = 0; kk < 8; kk++) {
            float4 a0 = *(const float4*)&sA[kk][ty * 8];
            float4 a1 = *(const float4*)&sA[kk][ty * 8 + 4];
            float4 b0 = *(const float4*)&sB[kk][tx * 8];
            float4 b1 = *(const float4*)&sB[kk][tx * 8 + 4];
            float a[8] = {a0.x, a0.y, a0.z, a0.w, a1.x, a1.y, a1.z, a1.w};
            float b[8] = {b0.x, b0.y, b0.z, b0.w, b1.x, b1.y, b1.z, b1.w};
            #pragma unroll
            for (int i = 0; i < 8; i++)
                #pragma unroll
                for (int j = 0; j < 8; j++)
                    acc[i][j] = fmaf(a[i], b[j], acc[i][j]);
        }
        __syncthreads();
    }

    #pragma unroll
    for (int i = 0; i < 8; i++) {
        int m = bm + ty * 8 + i;
        if (m < M) {
            #pragma unroll
            for (int j = 0; j < 8; j++) {
                int n = bn + tx * 8 + j;
                float v = acc[i][j] + bias[n];
                if (blocked)
                    C[((size_t)(n >> 6) * M + m) * 64 + (n & 63)] = v;
                else
                    C[(size_t)m * N + n] = v;
            }
        }
    }
}

// ---------------- fused LayerNorm + ReLU over rows of HID=256 (warp per row) ----
__global__ void ln_relu_kernel(float* __restrict__ h, const float* __restrict__ g,
                               const float* __restrict__ be, int M)
{
    int warp = (blockIdx.x * blockDim.x + threadIdx.x) >> 5;
    if (warp >= M) return;
    int lane = threadIdx.x & 31;

    float4* row = (float4*)(h + (size_t)warp * HID);
    float4 v0 = row[lane];
    float4 v1 = row[lane + 32];

    float s  = v0.x + v0.y + v0.z + v0.w + v1.x + v1.y + v1.z + v1.w;
    float sq = v0.x * v0.x + v0.y * v0.y + v0.z * v0.z + v0.w * v0.w
             + v1.x * v1.x + v1.y * v1.y + v1.z * v1.z + v1.w * v1.w;
    #pragma unroll
    for (int o = 16; o > 0; o >>= 1) {
        s  += __shfl_xor_sync(0xffffffffu, s, o);
        sq += __shfl_xor_sync(0xffffffffu, sq, o);
    }
    float mu   = s * (1.0f / 256.0f);
    float var  = sq * (1.0f / 256.0f) - mu * mu;
    float rstd = rsqrtf(var + LNEPS);

    const float4* g4 = (const float4*)g;
    const float4* b4 = (const float4*)be;
    float4 G0 = g4[lane], G1 = g4[lane + 32];
    float4 B0 = b4[lane], B1 = b4[lane + 32];

    v0.x = fmaxf((v0.x - mu) * rstd * G0.x + B0.x, 0.f);
    v0.y = fmaxf((v0.y - mu) * rstd * G0.y + B0.y, 0.f);
    v0.z = fmaxf((v0.z - mu) * rstd * G0.z + B0.z, 0.f);
    v0.w = fmaxf((v0.w - mu) * rstd * G0.w + B0.w, 0.f);
    v1.x = fmaxf((v1.x - mu) * rstd * G1.x + B1.x, 0.f);
    v1.y = fmaxf((v1.y - mu) * rstd * G1.y + B1.y, 0.f);
    v1.z = fmaxf((v1.z - mu) * rstd * G1.z + B1.z, 0.f);
    v1.w = fmaxf((v1.w - mu) * rstd * G1.w + B1.w, 0.f);

    row[lane]      = v0;
    row[lane + 32] = v1;
}

// ---------------- graph prep: CSR by dst ---------------------------------------
__global__ void zero_kernel(int* __restrict__ cnt, int* __restrict__ fill)
{
    int i = blockIdx.x * blockDim.x + threadIdx.x;
    if (i < NN) { cnt[i] = 0; fill[i] = 0; }
}

__global__ void deg_count_kernel(const int* __restrict__ dst, int* __restrict__ cnt, int E)
{
    int e = blockIdx.x * blockDim.x + threadIdx.x;
    if (e < E) atomicAdd(&cnt[dst[e]], 1);
}

__global__ void dis_kernel(const int* __restrict__ cnt, float* __restrict__ dis)
{
    int i = blockIdx.x * blockDim.x + threadIdx.x;
    if (i < NN) dis[i] = rsqrtf((float)(cnt[i] + 1));
}

__global__ void scan_partial(const int* __restrict__ cnt, int* __restrict__ rowptr,
                             int* __restrict__ bsum)
{
    __shared__ int s[256];
    int tid = threadIdx.x;
    int i = blockIdx.x * 256 + tid;
    int v = (i < NN) ? cnt[i] : 0;
    s[tid] = v;
    __syncthreads();
    #pragma unroll
    for (int o = 1; o < 256; o <<= 1) {
        int t = 0;
        if (tid >= o) t = s[tid - o];
        __syncthreads();
        if (tid >= o) s[tid] += t;
        __syncthreads();
    }
    if (i < NN) rowptr[i] = s[tid] - v;
    if (tid == 255) bsum[blockIdx.x] = s[255];
}

__global__ void scan_bsums(int* __restrict__ bsum, int nb)
{
    __shared__ int s[512];
    int tid = threadIdx.x;
    int v = (tid < nb) ? bsum[tid] : 0;
    s[tid] = v;
    __syncthreads();
    #pragma unroll
    for (int o = 1; o < 512; o <<= 1) {
        int t = 0;
        if (tid >= o) t = s[tid - o];
        __syncthreads();
        if (tid >= o) s[tid] += t;
        __syncthreads();
    }
    if (tid < nb) bsum[tid] = s[tid] - v;
}

__global__ void add_offsets(int* __restrict__ rowptr, const int* __restrict__ bsum, int E)
{
    int i = blockIdx.x * blockDim.x + threadIdx.x;
    if (i < NN) rowptr[i] += bsum[i >> 8];
    if (i == 0) rowptr[NN] = E;
}

__global__ void fill_kernel(const int* __restrict__ src, const int* __restrict__ dst,
                            const float* __restrict__ dis,
                            const int* __restrict__ rowptr, int* __restrict__ fill,
                            int2* __restrict__ csr, int E)
{
    int e = blockIdx.x * blockDim.x + threadIdx.x;
    if (e >= E) return;
    int si = src[e];
    int di = dst[e];
    int p = rowptr[di] + atomicAdd(&fill[di], 1);
    float w = ONEMA_F * dis[si] * dis[di];
    csr[p] = make_int2(si, __float_as_int(w));
}

// ---------------- APPNP step on a 64-channel block: warp per node ---------------
// carry/h0b are [node][64] blocked. out: blocked, or interleaved into d_out on
// the last step (out + node*128 + cb*64).
__global__ void appnp_step_kernel(const int* __restrict__ rowptr,
                                  const int2* __restrict__ csr,
                                  const float* __restrict__ dis,
                                  const float* __restrict__ h0b,
                                  const float* __restrict__ carry,
                                  float* __restrict__ out,
                                  int last, int cb)
{
    int node = (blockIdx.x * blockDim.x + threadIdx.x) >> 5;
    if (node >= NN) return;
    int lane = threadIdx.x & 31;

    const float2* c2 = (const float2*)carry;   // 32 float2 per node
    int beg = rowptr[node];
    int end = rowptr[node + 1];
    float ds = dis[node];
    float wself = ONEMA_F * ds * ds;

    float2 cv = c2[node * 32 + lane];
    float2 acc;
    acc.x = wself * cv.x;
    acc.y = wself * cv.y;

    int e = beg;
    for (; e + 3 < end; e += 4) {
        int2 e0 = __ldg(&csr[e]);
        int2 e1 = __ldg(&csr[e + 1]);
        int2 e2 = __ldg(&csr[e + 2]);
        int2 e3 = __ldg(&csr[e + 3]);
        float2 v0 = c2[e0.x * 32 + lane];
        float2 v1 = c2[e1.x * 32 + lane];
        float2 v2 = c2[e2.x * 32 + lane];
        float2 v3 = c2[e3.x * 32 + lane];
        float w0 = __int_as_float(e0.y), w1 = __int_as_float(e1.y);
        float w2 = __int_as_float(e2.y), w3 = __int_as_float(e3.y);
        acc.x = fmaf(w0, v0.x, acc.x); acc.y = fmaf(w0, v0.y, acc.y);
        acc.x = fmaf(w1, v1.x, acc.x); acc.y = fmaf(w1, v1.y, acc.y);
        acc.x = fmaf(w2, v2.x, acc.x); acc.y = fmaf(w2, v2.y, acc.y);
        acc.x = fmaf(w3, v3.x, acc.x); acc.y = fmaf(w3, v3.y, acc.y);
    }
    for (; e < end; e++) {
        int2 e0 = __ldg(&csr[e]);
        float w0 = __int_as_float(e0.y);
        float2 v0 = c2[e0.x * 32 + lane];
        acc.x = fmaf(w0, v0.x, acc.x);
        acc.y = fmaf(w0, v0.y, acc.y);
    }

    float2 h = ((const float2*)h0b)[node * 32 + lane];
    float2 o;
    o.x = fmaf(ALPHA_F, h.x, acc.x);
    o.y = fmaf(ALPHA_F, h.y, acc.y);

    if (last) {
        // interleave into [node][128] final layout; stream (no reuse) so output
        // lines don't evict the next channel-block's hot carry from L2
        __stcs((float2*)(out + (size_t)node * OUTC + cb * CB) + lane, o);
    } else {
        ((float2*)out)[node * 32 + lane] = o;
    }
}

// ---------------- launch --------------------------------------------------------
extern "C" void kernel_launch(void* const* d_in, const int* in_sizes, int n_in,
                              void* d_out, int out_size)
{
    const float* x     = (const float*)d_in[0];
    const int*   ei    = (const int*)  d_in[1];
    const float* W_in  = (const float*)d_in[2];
    const float* b_in  = (const float*)d_in[3];
    const float* W1    = (const float*)d_in[4];
    const float* b1    = (const float*)d_in[5];
    const float* g1    = (const float*)d_in[6];
    const float* be1   = (const float*)d_in[7];
    const float* W2    = (const float*)d_in[8];
    const float* b2    = (const float*)d_in[9];
    const float* g2    = (const float*)d_in[10];
    const float* be2   = (const float*)d_in[11];
    const float* W_out = (const float*)d_in[12];
    const float* b_out = (const float*)d_in[13];
    float* out = (float*)d_out;

    int E = in_sizes[1] / 2;
    if (E > EMAX) E = EMAX;
    const int* src = ei;
    const int* dst = ei + E;

    float *h1, *h2, *h0, *bA, *bB, *dis;
    int *cnt, *fill, *rowptr, *bsum;
    int2 *csr;
    cudaGetSymbolAddress((void**)&h1,      g_h1);
    cudaGetSymbolAddress((void**)&h2,      g_h2);
    cudaGetSymbolAddress((void**)&h0,      g_h0);
    cudaGetSymbolAddress((void**)&bA,      g_bufA);
    cudaGetSymbolAddress((void**)&bB,      g_bufB);
    cudaGetSymbolAddress((void**)&dis,     g_dis);
    cudaGetSymbolAddress((void**)&cnt,     g_cnt);
    cudaGetSymbolAddress((void**)&fill,    g_fill);
    cudaGetSymbolAddress((void**)&rowptr,  g_rowptr);
    cudaGetSymbolAddress((void**)&csr,     g_csr);
    cudaGetSymbolAddress((void**)&bsum,    g_bsum);

    const int mt  = (NN + 127) / 128;
    const int nb  = (NN + 255) / 256;
    const int ne  = (E + 255) / 256;

    // ---- graph prep (recomputed every call; no caching allowed) ----
    zero_kernel<<<nb, 256>>>(cnt, fill);
    deg_count_kernel<<<ne, 256>>>(dst, cnt, E);
    dis_kernel<<<nb, 256>>>(cnt, dis);
    scan_partial<<<nb, 256>>>(cnt, rowptr, bsum);
    scan_bsums<<<1, 512>>>(bsum, nb);
    add_offsets<<<nb, 256>>>(rowptr, bsum, E);
    fill_kernel<<<ne, 256>>>(src, dst, dis, rowptr, fill, csr, E);

    // ---- MLP (final GEMM writes blocked h0 layout for APPNP) ----
    sgemm_bias<<<dim3(HID / 128, mt), 256>>>(x,  W_in,  b_in,  h1, NN, INC, HID, 0);
    sgemm_bias<<<dim3(HID / 128, mt), 256>>>(h1, W1,    b1,    h2, NN, HID, HID, 0);
    ln_relu_kernel<<<(NN * 32 + 255) / 256, 256>>>(h2, g1, be1, NN);
    sgemm_bias<<<dim3(HID / 128, mt), 256>>>(h2, W2,    b2,    h1, NN, HID, HID, 0);
    ln_relu_kernel<<<(NN * 32 + 255) / 256, 256>>>(h1, g2, be2, NN);
    sgemm_bias<<<dim3(OUTC / 128, mt), 256>>>(h1, W_out, b_out, h0, NN, HID, OUTC, 1);

    // ---- APPNP: channel-blocked (L2-resident working set per block) ----
    const int step_blocks = (NN * 32 + 255) / 256;
    for (int cb = 0; cb < NCB; cb++) {
        const float* h0b = h0 + (size_t)cb * NN * CB;
        const float* carry = h0b;
        for (int t = 0; t < KSTEPS; t++) {
            int is_last = (t == KSTEPS - 1);
            float* o = is_last ? out : ((t & 1) ? bB : bA);
            appnp_step_kernel<<<step_blocks, 256>>>(rowptr, csr, dis, h0b, carry, o,
                                                    is_last, cb);
            carry = o;
        }
    }
}

// round 9
// speedup vs baseline: 1.2092x; 1.2092x over previous
#include <cuda_runtime.h>
#include <cuda_fp16.h>

#define NN      100000
#define INC     512
#define HID     256
#define OUTC    128
#define EMAX    1600000
#define KSTEPS  10
#define ALPHA_F 0.1f
#define ONEMA_F 0.9f
#define LNEPS   1e-5f

// ---------------- static device scratch (no allocation allowed) ----------------
__device__ float  g_h1[(size_t)NN * HID];
__device__ float  g_h2[(size_t)NN * HID];
__device__ float  g_h0[(size_t)NN * OUTC];      // fp32 teleport source
__device__ __half g_h016[(size_t)NN * OUTC];    // fp16 copy of h0
__device__ __half g_cA[(size_t)NN * OUTC];      // fp16 carry ping
__device__ __half g_cB[(size_t)NN * OUTC];      // fp16 carry pong
__device__ float  g_dis[NN];
__device__ int    g_cnt[NN];
__device__ int    g_fill[NN];
__device__ int    g_rowptr[NN + 1];
__device__ int2   g_csr[EMAX];                  // packed {src, weight-bits}
__device__ int    g_bsum[512];

// ---------------- fp32 SGEMM: C = A@B + bias, reg-prefetch pipeline -------------
__global__ void __launch_bounds__(256, 2)
sgemm_bias(const float* __restrict__ A, const float* __restrict__ B,
           const float* __restrict__ bias, float* __restrict__ C,
           int M, int K, int N)
{
    __shared__ float sA[8][128];
    __shared__ float sB[8][128];

    const int tid = threadIdx.x;
    const int bm  = blockIdx.y * 128;
    const int bn  = blockIdx.x * 128;
    const int tx  = tid & 15;
    const int ty  = tid >> 4;

    const int a_row = tid >> 1;
    const int a_k4  = (tid & 1) * 4;
    const bool m_ok = (bm + a_row) < M;
    const int b_k = tid >> 5;
    const int b_n = (tid & 31) * 4;

    const float* a_ptr = A + (size_t)(bm + a_row) * K + a_k4;
    const float* b_ptr = B + (size_t)b_k * N + (bn + b_n);

    float acc[8][8] = {};

    float4 avr = m_ok ? *(const float4*)a_ptr : make_float4(0.f, 0.f, 0.f, 0.f);
    float4 bvr = *(const float4*)b_ptr;

    const int nt = K / 8;
    for (int t = 0; t < nt; t++) {
        sA[a_k4 + 0][a_row] = avr.x;
        sA[a_k4 + 1][a_row] = avr.y;
        sA[a_k4 + 2][a_row] = avr.z;
        sA[a_k4 + 3][a_row] = avr.w;
        *(float4*)&sB[b_k][b_n] = bvr;
        __syncthreads();

        if (t + 1 < nt) {
            avr = m_ok ? *(const float4*)(a_ptr + (t + 1) * 8)
                       : make_float4(0.f, 0.f, 0.f, 0.f);
            bvr = *(const float4*)(b_ptr + (size_t)(t + 1) * 8 * N);
        }

        #pragma unroll
        for (int kk = 0; kk < 8; kk++) {
            float4 a0 = *(const float4*)&sA[kk][ty * 8];
            float4 a1 = *(const float4*)&sA[kk][ty * 8 + 4];
            float4 b0 = *(const float4*)&sB[kk][tx * 8];
            float4 b1 = *(const float4*)&sB[kk][tx * 8 + 4];
            float a[8] = {a0.x, a0.y, a0.z, a0.w, a1.x, a1.y, a1.z, a1.w};
            float b[8] = {b0.x, b0.y, b0.z, b0.w, b1.x, b1.y, b1.z, b1.w};
            #pragma unroll
            for (int i = 0; i < 8; i++)
                #pragma unroll
                for (int j = 0; j < 8; j++)
                    acc[i][j] = fmaf(a[i], b[j], acc[i][j]);
        }
        __syncthreads();
    }

    #pragma unroll
    for (int i = 0; i < 8; i++) {
        int m = bm + ty * 8 + i;
        if (m < M) {
            #pragma unroll
            for (int j = 0; j < 8; j++) {
                int n = bn + tx * 8 + j;
                C[(size_t)m * N + n] = acc[i][j] + bias[n];
            }
        }
    }
}

// ---------------- fused LayerNorm + ReLU (warp per row of 256) ------------------
__global__ void ln_relu_kernel(float* __restrict__ h, const float* __restrict__ g,
                               const float* __restrict__ be, int M)
{
    int warp = (blockIdx.x * blockDim.x + threadIdx.x) >> 5;
    if (warp >= M) return;
    int lane = threadIdx.x & 31;

    float4* row = (float4*)(h + (size_t)warp * HID);
    float4 v0 = row[lane];
    float4 v1 = row[lane + 32];

    float s  = v0.x + v0.y + v0.z + v0.w + v1.x + v1.y + v1.z + v1.w;
    float sq = v0.x * v0.x + v0.y * v0.y + v0.z * v0.z + v0.w * v0.w
             + v1.x * v1.x + v1.y * v1.y + v1.z * v1.z + v1.w * v1.w;
    #pragma unroll
    for (int o = 16; o > 0; o >>= 1) {
        s  += __shfl_xor_sync(0xffffffffu, s, o);
        sq += __shfl_xor_sync(0xffffffffu, sq, o);
    }
    float mu   = s * (1.0f / 256.0f);
    float var  = sq * (1.0f / 256.0f) - mu * mu;
    float rstd = rsqrtf(var + LNEPS);

    const float4* g4 = (const float4*)g;
    const float4* b4 = (const float4*)be;
    float4 G0 = g4[lane], G1 = g4[lane + 32];
    float4 B0 = b4[lane], B1 = b4[lane + 32];

    v0.x = fmaxf((v0.x - mu) * rstd * G0.x + B0.x, 0.f);
    v0.y = fmaxf((v0.y - mu) * rstd * G0.y + B0.y, 0.f);
    v0.z = fmaxf((v0.z - mu) * rstd * G0.z + B0.z, 0.f);
    v0.w = fmaxf((v0.w - mu) * rstd * G0.w + B0.w, 0.f);
    v1.x = fmaxf((v1.x - mu) * rstd * G1.x + B1.x, 0.f);
    v1.y = fmaxf((v1.y - mu) * rstd * G1.y + B1.y, 0.f);
    v1.z = fmaxf((v1.z - mu) * rstd * G1.z + B1.z, 0.f);
    v1.w = fmaxf((v1.w - mu) * rstd * G1.w + B1.w, 0.f);

    row[lane]      = v0;
    row[lane + 32] = v1;
}

// ---------------- graph prep: CSR by dst ---------------------------------------
__global__ void zero_kernel(int* __restrict__ cnt, int* __restrict__ fill)
{
    int i = blockIdx.x * blockDim.x + threadIdx.x;
    if (i < NN) { cnt[i] = 0; fill[i] = 0; }
}

__global__ void deg_count_kernel(const int* __restrict__ dst, int* __restrict__ cnt, int E)
{
    int e = blockIdx.x * blockDim.x + threadIdx.x;
    if (e < E) atomicAdd(&cnt[dst[e]], 1);
}

__global__ void dis_kernel(const int* __restrict__ cnt, float* __restrict__ dis)
{
    int i = blockIdx.x * blockDim.x + threadIdx.x;
    if (i < NN) dis[i] = rsqrtf((float)(cnt[i] + 1));
}

__global__ void scan_partial(const int* __restrict__ cnt, int* __restrict__ rowptr,
                             int* __restrict__ bsum)
{
    __shared__ int s[256];
    int tid = threadIdx.x;
    int i = blockIdx.x * 256 + tid;
    int v = (i < NN) ? cnt[i] : 0;
    s[tid] = v;
    __syncthreads();
    #pragma unroll
    for (int o = 1; o < 256; o <<= 1) {
        int t = 0;
        if (tid >= o) t = s[tid - o];
        __syncthreads();
        if (tid >= o) s[tid] += t;
        __syncthreads();
    }
    if (i < NN) rowptr[i] = s[tid] - v;
    if (tid == 255) bsum[blockIdx.x] = s[255];
}

__global__ void scan_bsums(int* __restrict__ bsum, int nb)
{
    __shared__ int s[512];
    int tid = threadIdx.x;
    int v = (tid < nb) ? bsum[tid] : 0;
    s[tid] = v;
    __syncthreads();
    #pragma unroll
    for (int o = 1; o < 512; o <<= 1) {
        int t = 0;
        if (tid >= o) t = s[tid - o];
        __syncthreads();
        if (tid >= o) s[tid] += t;
        __syncthreads();
    }
    if (tid < nb) bsum[tid] = s[tid] - v;
}

__global__ void add_offsets(int* __restrict__ rowptr, const int* __restrict__ bsum, int E)
{
    int i = blockIdx.x * blockDim.x + threadIdx.x;
    if (i < NN) rowptr[i] += bsum[i >> 8];
    if (i == 0) rowptr[NN] = E;
}

__global__ void fill_kernel(const int* __restrict__ src, const int* __restrict__ dst,
                            const float* __restrict__ dis,
                            const int* __restrict__ rowptr, int* __restrict__ fill,
                            int2* __restrict__ csr, int E)
{
    int e = blockIdx.x * blockDim.x + threadIdx.x;
    if (e >= E) return;
    int si = src[e];
    int di = dst[e];
    int p = rowptr[di] + atomicAdd(&fill[di], 1);
    float w = ONEMA_F * dis[si] * dis[di];
    csr[p] = make_int2(si, __float_as_int(w));
}

// ---------------- fp32 -> fp16 convert (4 elems / thread) ----------------------
__global__ void f2h_kernel(const float* __restrict__ in, __half* __restrict__ out)
{
    int idx = blockIdx.x * blockDim.x + threadIdx.x;   // over NN*32 float4s
    if (idx >= NN * (OUTC / 4)) return;
    float4 v = ((const float4*)in)[idx];
    __half2 lo = __floats2half2_rn(v.x, v.y);
    __half2 hi = __floats2half2_rn(v.z, v.w);
    uint2 o;
    o.x = *(unsigned*)&lo;
    o.y = *(unsigned*)&hi;
    ((uint2*)out)[idx] = o;
}

// ---------------- APPNP step: warp per node, fp16 carry gathers ----------------
// out[i] = alpha*h0[i] + (1-alpha)/deg[i]*carry[i] + sum_e w_e*carry[src_e]
__global__ void appnp_step_kernel(const int* __restrict__ rowptr,
                                  const int2* __restrict__ csr,
                                  const float* __restrict__ dis,
                                  const float* __restrict__ h0f,
                                  const __half* __restrict__ h016,
                                  const __half* __restrict__ carry,
                                  __half* __restrict__ out16,
                                  float* __restrict__ outf,
                                  int last)
{
    int node = (blockIdx.x * blockDim.x + threadIdx.x) >> 5;
    if (node >= NN) return;
    int lane = threadIdx.x & 31;

    const uint2* c = (const uint2*)carry;   // 4 halves (8B) per lane, 32 lanes = 256B/row
    int beg = rowptr[node];
    int end = rowptr[node + 1];
    float ds = dis[node];
    float wself = ONEMA_F * ds * ds;

    uint2 cv = c[node * 32 + lane];
    float2 c0 = __half22float2(*(__half2*)&cv.x);
    float2 c1 = __half22float2(*(__half2*)&cv.y);
    float4 acc;
    acc.x = wself * c0.x; acc.y = wself * c0.y;
    acc.z = wself * c1.x; acc.w = wself * c1.y;

    int e = beg;
    for (; e + 3 < end; e += 4) {
        int2 e0 = __ldg(&csr[e]);
        int2 e1 = __ldg(&csr[e + 1]);
        int2 e2 = __ldg(&csr[e + 2]);
        int2 e3 = __ldg(&csr[e + 3]);
        uint2 p0 = c[e0.x * 32 + lane];
        uint2 p1 = c[e1.x * 32 + lane];
        uint2 p2 = c[e2.x * 32 + lane];
        uint2 p3 = c[e3.x * 32 + lane];
        float w0 = __int_as_float(e0.y), w1 = __int_as_float(e1.y);
        float w2 = __int_as_float(e2.y), w3 = __int_as_float(e3.y);
        float2 a0 = __half22float2(*(__half2*)&p0.x), b0 = __half22float2(*(__half2*)&p0.y);
        float2 a1 = __half22float2(*(__half2*)&p1.x), b1 = __half22float2(*(__half2*)&p1.y);
        float2 a2 = __half22float2(*(__half2*)&p2.x), b2 = __half22float2(*(__half2*)&p2.y);
        float2 a3 = __half22float2(*(__half2*)&p3.x), b3 = __half22float2(*(__half2*)&p3.y);
        acc.x = fmaf(w0, a0.x, acc.x); acc.y = fmaf(w0, a0.y, acc.y);
        acc.z = fmaf(w0, b0.x, acc.z); acc.w = fmaf(w0, b0.y, acc.w);
        acc.x = fmaf(w1, a1.x, acc.x); acc.y = fmaf(w1, a1.y, acc.y);
        acc.z = fmaf(w1, b1.x, acc.z); acc.w = fmaf(w1, b1.y, acc.w);
        acc.x = fmaf(w2, a2.x, acc.x); acc.y = fmaf(w2, a2.y, acc.y);
        acc.z = fmaf(w2, b2.x, acc.z); acc.w = fmaf(w2, b2.y, acc.w);
        acc.x = fmaf(w3, a3.x, acc.x); acc.y = fmaf(w3, a3.y, acc.y);
        acc.z = fmaf(w3, b3.x, acc.z); acc.w = fmaf(w3, b3.y, acc.w);
    }
    for (; e < end; e++) {
        int2 e0 = __ldg(&csr[e]);
        float w0 = __int_as_float(e0.y);
        uint2 p0 = c[e0.x * 32 + lane];
        float2 a0 = __half22float2(*(__half2*)&p0.x);
        float2 b0 = __half22float2(*(__half2*)&p0.y);
        acc.x = fmaf(w0, a0.x, acc.x); acc.y = fmaf(w0, a0.y, acc.y);
        acc.z = fmaf(w0, b0.x, acc.z); acc.w = fmaf(w0, b0.y, acc.w);
    }

    if (last) {
        // final step: fp32 teleport + fp32 output (streamed, no reuse)
        float4 h = __ldcs((const float4*)h0f + node * 32 + lane);
        float4 o;
        o.x = fmaf(ALPHA_F, h.x, acc.x);
        o.y = fmaf(ALPHA_F, h.y, acc.y);
        o.z = fmaf(ALPHA_F, h.z, acc.z);
        o.w = fmaf(ALPHA_F, h.w, acc.w);
        __stcs((float4*)outf + node * 32 + lane, o);
    } else {
        // intermediate: fp16 teleport read, fp16 carry write
        uint2 hp = ((const uint2*)h016)[node * 32 + lane];
        float2 h0v = __half22float2(*(__half2*)&hp.x);
        float2 h1v = __half22float2(*(__half2*)&hp.y);
        float2 o0, o1;
        o0.x = fmaf(ALPHA_F, h0v.x, acc.x);
        o0.y = fmaf(ALPHA_F, h0v.y, acc.y);
        o1.x = fmaf(ALPHA_F, h1v.x, acc.z);
        o1.y = fmaf(ALPHA_F, h1v.y, acc.w);
        __half2 q0 = __floats2half2_rn(o0.x, o0.y);
        __half2 q1 = __floats2half2_rn(o1.x, o1.y);
        uint2 ov;
        ov.x = *(unsigned*)&q0;
        ov.y = *(unsigned*)&q1;
        ((uint2*)out16)[node * 32 + lane] = ov;
    }
}

// ---------------- launch --------------------------------------------------------
extern "C" void kernel_launch(void* const* d_in, const int* in_sizes, int n_in,
                              void* d_out, int out_size)
{
    const float* x     = (const float*)d_in[0];
    const int*   ei    = (const int*)  d_in[1];
    const float* W_in  = (const float*)d_in[2];
    const float* b_in  = (const float*)d_in[3];
    const float* W1    = (const float*)d_in[4];
    const float* b1    = (const float*)d_in[5];
    const float* g1    = (const float*)d_in[6];
    const float* be1   = (const float*)d_in[7];
    const float* W2    = (const float*)d_in[8];
    const float* b2    = (const float*)d_in[9];
    const float* g2    = (const float*)d_in[10];
    const float* be2   = (const float*)d_in[11];
    const float* W_out = (const float*)d_in[12];
    const float* b_out = (const float*)d_in[13];
    float* out = (float*)d_out;

    int E = in_sizes[1] / 2;
    if (E > EMAX) E = EMAX;
    const int* src = ei;
    const int* dst = ei + E;

    float *h1, *h2, *h0, *dis;
    __half *h016, *cA, *cB;
    int *cnt, *fill, *rowptr, *bsum;
    int2 *csr;
    cudaGetSymbolAddress((void**)&h1,     g_h1);
    cudaGetSymbolAddress((void**)&h2,     g_h2);
    cudaGetSymbolAddress((void**)&h0,     g_h0);
    cudaGetSymbolAddress((void**)&h016,   g_h016);
    cudaGetSymbolAddress((void**)&cA,     g_cA);
    cudaGetSymbolAddress((void**)&cB,     g_cB);
    cudaGetSymbolAddress((void**)&dis,    g_dis);
    cudaGetSymbolAddress((void**)&cnt,    g_cnt);
    cudaGetSymbolAddress((void**)&fill,   g_fill);
    cudaGetSymbolAddress((void**)&rowptr, g_rowptr);
    cudaGetSymbolAddress((void**)&csr,    g_csr);
    cudaGetSymbolAddress((void**)&bsum,   g_bsum);

    const int mt = (NN + 127) / 128;
    const int nb = (NN + 255) / 256;
    const int ne = (E + 255) / 256;

    // ---- graph prep (recomputed every call; no caching allowed) ----
    zero_kernel<<<nb, 256>>>(cnt, fill);
    deg_count_kernel<<<ne, 256>>>(dst, cnt, E);
    dis_kernel<<<nb, 256>>>(cnt, dis);
    scan_partial<<<nb, 256>>>(cnt, rowptr, bsum);
    scan_bsums<<<1, 512>>>(bsum, nb);
    add_offsets<<<nb, 256>>>(rowptr, bsum, E);
    fill_kernel<<<ne, 256>>>(src, dst, dis, rowptr, fill, csr, E);

    // ---- MLP ----
    sgemm_bias<<<dim3(HID / 128, mt), 256>>>(x,  W_in,  b_in,  h1, NN, INC, HID);
    sgemm_bias<<<dim3(HID / 128, mt), 256>>>(h1, W1,    b1,    h2, NN, HID, HID);
    ln_relu_kernel<<<(NN * 32 + 255) / 256, 256>>>(h2, g1, be1, NN);
    sgemm_bias<<<dim3(HID / 128, mt), 256>>>(h2, W2,    b2,    h1, NN, HID, HID);
    ln_relu_kernel<<<(NN * 32 + 255) / 256, 256>>>(h1, g2, be2, NN);
    sgemm_bias<<<dim3(OUTC / 128, mt), 256>>>(h1, W_out, b_out, h0, NN, HID, OUTC);

    // fp16 copy of h0 = initial carry and teleport source for steps 0..8
    const int cvt_blocks = (NN * 32 + 255) / 256;
    f2h_kernel<<<cvt_blocks, 256>>>(h0, h016);

    // ---- APPNP: 10 fused pull steps, fp16 carry, fp32 final ----
    const __half* carry = h016;
    const int step_blocks = (NN * 32 + 255) / 256;
    for (int t = 0; t < KSTEPS; t++) {
        int is_last = (t == KSTEPS - 1);
        __half* o16 = (t & 1) ? cB : cA;
        appnp_step_kernel<<<step_blocks, 256>>>(rowptr, csr, dis, h0, h016,
                                                carry, o16, out, is_last);
        carry = o16;
    }
}

// round 11
// speedup vs baseline: 1.2432x; 1.0281x over previous
#include <cuda_runtime.h>
#include <cuda_fp16.h>

#define NN      100000
#define INC     512
#define HID     256
#define OUTC    128
#define EMAX    1600000
#define KSTEPS  10
#define ALPHA_F 0.1f
#define ONEMA_F 0.9f
#define LNEPS   1e-5f

// ---------------- static device scratch (no allocation allowed) ----------------
__device__ float  g_h1[(size_t)NN * HID];
__device__ float  g_h2[(size_t)NN * HID];
__device__ float  g_h0[(size_t)NN * OUTC];      // fp32 teleport source
__device__ __half g_h016[(size_t)NN * OUTC];    // fp16 copy of h0
__device__ __half g_cA[(size_t)NN * OUTC];      // fp16 carry ping
__device__ __half g_cB[(size_t)NN * OUTC];      // fp16 carry pong
__device__ float  g_dis[NN];
__device__ int    g_cnt[NN];
__device__ int    g_fill[NN];
__device__ int    g_rowptr[NN + 1];
__device__ int2   g_csr[EMAX];                  // packed {src, weight-bits}
__device__ int    g_bsum[512];

// ---------------- fp32 SGEMM: C = A@B + bias, reg-prefetch pipeline -------------
__global__ void __launch_bounds__(256, 2)
sgemm_bias(const float* __restrict__ A, const float* __restrict__ B,
           const float* __restrict__ bias, float* __restrict__ C,
           int M, int K, int N)
{
    __shared__ float sA[8][128];
    __shared__ float sB[8][128];

    const int tid = threadIdx.x;
    const int bm  = blockIdx.y * 128;
    const int bn  = blockIdx.x * 128;
    const int tx  = tid & 15;
    const int ty  = tid >> 4;

    const int a_row = tid >> 1;
    const int a_k4  = (tid & 1) * 4;
    const bool m_ok = (bm + a_row) < M;
    const int b_k = tid >> 5;
    const int b_n = (tid & 31) * 4;

    const float* a_ptr = A + (size_t)(bm + a_row) * K + a_k4;
    const float* b_ptr = B + (size_t)b_k * N + (bn + b_n);

    float acc[8][8] = {};

    float4 avr = m_ok ? *(const float4*)a_ptr : make_float4(0.f, 0.f, 0.f, 0.f);
    float4 bvr = *(const float4*)b_ptr;

    const int nt = K / 8;
    for (int t = 0; t < nt; t++) {
        sA[a_k4 + 0][a_row] = avr.x;
        sA[a_k4 + 1][a_row] = avr.y;
        sA[a_k4 + 2][a_row] = avr.z;
        sA[a_k4 + 3][a_row] = avr.w;
        *(float4*)&sB[b_k][b_n] = bvr;
        __syncthreads();

        if (t + 1 < nt) {
            avr = m_ok ? *(const float4*)(a_ptr + (t + 1) * 8)
                       : make_float4(0.f, 0.f, 0.f, 0.f);
            bvr = *(const float4*)(b_ptr + (size_t)(t + 1) * 8 * N);
        }

        #pragma unroll
        for (int kk = 0; kk < 8; kk++) {
            float4 a0 = *(const float4*)&sA[kk][ty * 8];
            float4 a1 = *(const float4*)&sA[kk][ty * 8 + 4];
            float4 b0 = *(const float4*)&sB[kk][tx * 8];
            float4 b1 = *(const float4*)&sB[kk][tx * 8 + 4];
            float a[8] = {a0.x, a0.y, a0.z, a0.w, a1.x, a1.y, a1.z, a1.w};
            float b[8] = {b0.x, b0.y, b0.z, b0.w, b1.x, b1.y, b1.z, b1.w};
            #pragma unroll
            for (int i = 0; i < 8; i++)
                #pragma unroll
                for (int j = 0; j < 8; j++)
                    acc[i][j] = fmaf(a[i], b[j], acc[i][j]);
        }
        __syncthreads();
    }

    #pragma unroll
    for (int i = 0; i < 8; i++) {
        int m = bm + ty * 8 + i;
        if (m < M) {
            #pragma unroll
            for (int j = 0; j < 8; j++) {
                int n = bn + tx * 8 + j;
                C[(size_t)m * N + n] = acc[i][j] + bias[n];
            }
        }
    }
}

// ---------------- fused LayerNorm + ReLU (warp per row of 256) ------------------
__global__ void ln_relu_kernel(float* __restrict__ h, const float* __restrict__ g,
                               const float* __restrict__ be, int M)
{
    int warp = (blockIdx.x * blockDim.x + threadIdx.x) >> 5;
    if (warp >= M) return;
    int lane = threadIdx.x & 31;

    float4* row = (float4*)(h + (size_t)warp * HID);
    float4 v0 = row[lane];
    float4 v1 = row[lane + 32];

    float s  = v0.x + v0.y + v0.z + v0.w + v1.x + v1.y + v1.z + v1.w;
    float sq = v0.x * v0.x + v0.y * v0.y + v0.z * v0.z + v0.w * v0.w
             + v1.x * v1.x + v1.y * v1.y + v1.z * v1.z + v1.w * v1.w;
    #pragma unroll
    for (int o = 16; o > 0; o >>= 1) {
        s  += __shfl_xor_sync(0xffffffffu, s, o);
        sq += __shfl_xor_sync(0xffffffffu, sq, o);
    }
    float mu   = s * (1.0f / 256.0f);
    float var  = sq * (1.0f / 256.0f) - mu * mu;
    float rstd = rsqrtf(var + LNEPS);

    const float4* g4 = (const float4*)g;
    const float4* b4 = (const float4*)be;
    float4 G0 = g4[lane], G1 = g4[lane + 32];
    float4 B0 = b4[lane], B1 = b4[lane + 32];

    v0.x = fmaxf((v0.x - mu) * rstd * G0.x + B0.x, 0.f);
    v0.y = fmaxf((v0.y - mu) * rstd * G0.y + B0.y, 0.f);
    v0.z = fmaxf((v0.z - mu) * rstd * G0.z + B0.z, 0.f);
    v0.w = fmaxf((v0.w - mu) * rstd * G0.w + B0.w, 0.f);
    v1.x = fmaxf((v1.x - mu) * rstd * G1.x + B1.x, 0.f);
    v1.y = fmaxf((v1.y - mu) * rstd * G1.y + B1.y, 0.f);
    v1.z = fmaxf((v1.z - mu) * rstd * G1.z + B1.z, 0.f);
    v1.w = fmaxf((v1.w - mu) * rstd * G1.w + B1.w, 0.f);

    row[lane]      = v0;
    row[lane + 32] = v1;
}

// ---------------- graph prep: CSR by dst ---------------------------------------
__global__ void zero_kernel(int* __restrict__ cnt, int* __restrict__ fill)
{
    int i = blockIdx.x * blockDim.x + threadIdx.x;
    if (i < NN) { cnt[i] = 0; fill[i] = 0; }
}

__global__ void deg_count_kernel(const int* __restrict__ dst, int* __restrict__ cnt, int E)
{
    int e = blockIdx.x * blockDim.x + threadIdx.x;
    if (e < E) atomicAdd(&cnt[dst[e]], 1);
}

__global__ void dis_kernel(const int* __restrict__ cnt, float* __restrict__ dis)
{
    int i = blockIdx.x * blockDim.x + threadIdx.x;
    if (i < NN) dis[i] = rsqrtf((float)(cnt[i] + 1));
}

__global__ void scan_partial(const int* __restrict__ cnt, int* __restrict__ rowptr,
                             int* __restrict__ bsum)
{
    __shared__ int s[256];
    int tid = threadIdx.x;
    int i = blockIdx.x * 256 + tid;
    int v = (i < NN) ? cnt[i] : 0;
    s[tid] = v;
    __syncthreads();
    #pragma unroll
    for (int o = 1; o < 256; o <<= 1) {
        int t = 0;
        if (tid >= o) t = s[tid - o];
        __syncthreads();
        if (tid >= o) s[tid] += t;
        __syncthreads();
    }
    if (i < NN) rowptr[i] = s[tid] - v;
    if (tid == 255) bsum[blockIdx.x] = s[255];
}

__global__ void scan_bsums(int* __restrict__ bsum, int nb)
{
    __shared__ int s[512];
    int tid = threadIdx.x;
    int v = (tid < nb) ? bsum[tid] : 0;
    s[tid] = v;
    __syncthreads();
    #pragma unroll
    for (int o = 1; o < 512; o <<= 1) {
        int t = 0;
        if (tid >= o) t = s[tid - o];
        __syncthreads();
        if (tid >= o) s[tid] += t;
        __syncthreads();
    }
    if (tid < nb) bsum[tid] = s[tid] - v;
}

__global__ void add_offsets(int* __restrict__ rowptr, const int* __restrict__ bsum, int E)
{
    int i = blockIdx.x * blockDim.x + threadIdx.x;
    if (i < NN) rowptr[i] += bsum[i >> 8];
    if (i == 0) rowptr[NN] = E;
}

__global__ void fill_kernel(const int* __restrict__ src, const int* __restrict__ dst,
                            const float* __restrict__ dis,
                            const int* __restrict__ rowptr, int* __restrict__ fill,
                            int2* __restrict__ csr, int E)
{
    int e = blockIdx.x * blockDim.x + threadIdx.x;
    if (e >= E) return;
    int si = src[e];
    int di = dst[e];
    int p = rowptr[di] + atomicAdd(&fill[di], 1);
    float w = ONEMA_F * dis[si] * dis[di];
    csr[p] = make_int2(si, __float_as_int(w));
}

// ---------------- fp32 -> fp16 convert (4 elems / thread) ----------------------
__global__ void f2h_kernel(const float* __restrict__ in, __half* __restrict__ out)
{
    int idx = blockIdx.x * blockDim.x + threadIdx.x;   // over NN*32 float4s
    if (idx >= NN * (OUTC / 4)) return;
    float4 v = ((const float4*)in)[idx];
    __half2 lo = __floats2half2_rn(v.x, v.y);
    __half2 hi = __floats2half2_rn(v.z, v.w);
    uint2 o;
    o.x = *(unsigned*)&lo;
    o.y = *(unsigned*)&hi;
    ((uint2*)out)[idx] = o;
}

// ---------------- APPNP step: 2 nodes per warp (16 lanes each), uint4 gathers ---
// out[i] = alpha*h0[i] + (1-alpha)/deg[i]*carry[i] + sum_e w_e*carry[src_e]
// Each lane handles 8 channels (uint4 = 8 halves); 16 lanes cover 128 channels.
__global__ void __launch_bounds__(256)
appnp_step_kernel(const int* __restrict__ rowptr,
                  const int2* __restrict__ csr,
                  const float* __restrict__ dis,
                  const float* __restrict__ h0f,
                  const __half* __restrict__ h016,
                  const __half* __restrict__ carry,
                  __half* __restrict__ out16,
                  float* __restrict__ outf,
                  int last)
{
    int warp_id = (blockIdx.x * blockDim.x + threadIdx.x) >> 5;
    int lane = threadIdx.x & 31;
    int node = warp_id * 2 + (lane >> 4);
    int l16  = lane & 15;
    if (node >= NN) return;

    const uint4* c = (const uint4*)carry;   // 16 uint4 per node row (256 B)
    int beg = rowptr[node];
    int end = rowptr[node + 1];
    float ds = dis[node];
    float wself = ONEMA_F * ds * ds;

    uint4 cv = c[node * 16 + l16];
    float2 s0 = __half22float2(*(__half2*)&cv.x);
    float2 s1 = __half22float2(*(__half2*)&cv.y);
    float2 s2 = __half22float2(*(__half2*)&cv.z);
    float2 s3 = __half22float2(*(__half2*)&cv.w);
    float acc[8];
    acc[0] = wself * s0.x; acc[1] = wself * s0.y;
    acc[2] = wself * s1.x; acc[3] = wself * s1.y;
    acc[4] = wself * s2.x; acc[5] = wself * s2.y;
    acc[6] = wself * s3.x; acc[7] = wself * s3.y;

    int e = beg;
    // 2-way unroll: 2 gathers (x2 nodes across the warp) in flight per iter
    for (; e + 1 < end; e += 2) {
        int2 c0 = __ldg(&csr[e]);
        int2 c1 = __ldg(&csr[e + 1]);
        uint4 p0 = c[c0.x * 16 + l16];
        uint4 p1 = c[c1.x * 16 + l16];
        float w0 = __int_as_float(c0.y);
        float w1 = __int_as_float(c1.y);
        float2 a0 = __half22float2(*(__half2*)&p0.x);
        float2 a1 = __half22float2(*(__half2*)&p0.y);
        float2 a2 = __half22float2(*(__half2*)&p0.z);
        float2 a3 = __half22float2(*(__half2*)&p0.w);
        acc[0] = fmaf(w0, a0.x, acc[0]); acc[1] = fmaf(w0, a0.y, acc[1]);
        acc[2] = fmaf(w0, a1.x, acc[2]); acc[3] = fmaf(w0, a1.y, acc[3]);
        acc[4] = fmaf(w0, a2.x, acc[4]); acc[5] = fmaf(w0, a2.y, acc[5]);
        acc[6] = fmaf(w0, a3.x, acc[6]); acc[7] = fmaf(w0, a3.y, acc[7]);
        float2 b0 = __half22float2(*(__half2*)&p1.x);
        float2 b1 = __half22float2(*(__half2*)&p1.y);
        float2 b2 = __half22float2(*(__half2*)&p1.z);
        float2 b3 = __half22float2(*(__half2*)&p1.w);
        acc[0] = fmaf(w1, b0.x, acc[0]); acc[1] = fmaf(w1, b0.y, acc[1]);
        acc[2] = fmaf(w1, b1.x, acc[2]); acc[3] = fmaf(w1, b1.y, acc[3]);
        acc[4] = fmaf(w1, b2.x, acc[4]); acc[5] = fmaf(w1, b2.y, acc[5]);
        acc[6] = fmaf(w1, b3.x, acc[6]); acc[7] = fmaf(w1, b3.y, acc[7]);
    }
    if (e < end) {
        int2 c0 = __ldg(&csr[e]);
        uint4 p0 = c[c0.x * 16 + l16];
        float w0 = __int_as_float(c0.y);
        float2 a0 = __half22float2(*(__half2*)&p0.x);
        float2 a1 = __half22float2(*(__half2*)&p0.y);
        float2 a2 = __half22float2(*(__half2*)&p0.z);
        float2 a3 = __half22float2(*(__half2*)&p0.w);
        acc[0] = fmaf(w0, a0.x, acc[0]); acc[1] = fmaf(w0, a0.y, acc[1]);
        acc[2] = fmaf(w0, a1.x, acc[2]); acc[3] = fmaf(w0, a1.y, acc[3]);
        acc[4] = fmaf(w0, a2.x, acc[4]); acc[5] = fmaf(w0, a2.y, acc[5]);
        acc[6] = fmaf(w0, a3.x, acc[6]); acc[7] = fmaf(w0, a3.y, acc[7]);
    }

    if (last) {
        // final step: fp32 teleport + fp32 output (streamed, no reuse)
        const float4* h4 = (const float4*)h0f + node * 32 + l16 * 2;
        float4 ha = __ldcs(h4);
        float4 hb = __ldcs(h4 + 1);
        float4 oa, ob;
        oa.x = fmaf(ALPHA_F, ha.x, acc[0]);
        oa.y = fmaf(ALPHA_F, ha.y, acc[1]);
        oa.z = fmaf(ALPHA_F, ha.z, acc[2]);
        oa.w = fmaf(ALPHA_F, ha.w, acc[3]);
        ob.x = fmaf(ALPHA_F, hb.x, acc[4]);
        ob.y = fmaf(ALPHA_F, hb.y, acc[5]);
        ob.z = fmaf(ALPHA_F, hb.z, acc[6]);
        ob.w = fmaf(ALPHA_F, hb.w, acc[7]);
        float4* o4 = (float4*)outf + node * 32 + l16 * 2;
        __stcs(o4, oa);
        __stcs(o4 + 1, ob);
    } else {
        // intermediate: fp16 teleport read, fp16 carry write
        uint4 hp = ((const uint4*)h016)[node * 16 + l16];
        float2 h0v = __half22float2(*(__half2*)&hp.x);
        float2 h1v = __half22float2(*(__half2*)&hp.y);
        float2 h2v = __half22float2(*(__half2*)&hp.z);
        float2 h3v = __half22float2(*(__half2*)&hp.w);
        __half2 q0 = __floats2half2_rn(fmaf(ALPHA_F, h0v.x, acc[0]),
                                       fmaf(ALPHA_F, h0v.y, acc[1]));
        __half2 q1 = __floats2half2_rn(fmaf(ALPHA_F, h1v.x, acc[2]),
                                       fmaf(ALPHA_F, h1v.y, acc[3]));
        __half2 q2 = __floats2half2_rn(fmaf(ALPHA_F, h2v.x, acc[4]),
                                       fmaf(ALPHA_F, h2v.y, acc[5]));
        __half2 q3 = __floats2half2_rn(fmaf(ALPHA_F, h3v.x, acc[6]),
                                       fmaf(ALPHA_F, h3v.y, acc[7]));
        uint4 ov;
        ov.x = *(unsigned*)&q0;
        ov.y = *(unsigned*)&q1;
        ov.z = *(unsigned*)&q2;
        ov.w = *(unsigned*)&q3;
        ((uint4*)out16)[node * 16 + l16] = ov;
    }
}

// ---------------- launch --------------------------------------------------------
extern "C" void kernel_launch(void* const* d_in, const int* in_sizes, int n_in,
                              void* d_out, int out_size)
{
    const float* x     = (const float*)d_in[0];
    const int*   ei    = (const int*)  d_in[1];
    const float* W_in  = (const float*)d_in[2];
    const float* b_in  = (const float*)d_in[3];
    const float* W1    = (const float*)d_in[4];
    const float* b1    = (const float*)d_in[5];
    const float* g1    = (const float*)d_in[6];
    const float* be1   = (const float*)d_in[7];
    const float* W2    = (const float*)d_in[8];
    const float* b2    = (const float*)d_in[9];
    const float* g2    = (const float*)d_in[10];
    const float* be2   = (const float*)d_in[11];
    const float* W_out = (const float*)d_in[12];
    const float* b_out = (const float*)d_in[13];
    float* out = (float*)d_out;

    int E = in_sizes[1] / 2;
    if (E > EMAX) E = EMAX;
    const int* src = ei;
    const int* dst = ei + E;

    float *h1, *h2, *h0, *dis;
    __half *h016, *cA, *cB;
    int *cnt, *fill, *rowptr, *bsum;
    int2 *csr;
    cudaGetSymbolAddress((void**)&h1,     g_h1);
    cudaGetSymbolAddress((void**)&h2,     g_h2);
    cudaGetSymbolAddress((void**)&h0,     g_h0);
    cudaGetSymbolAddress((void**)&h016,   g_h016);
    cudaGetSymbolAddress((void**)&cA,     g_cA);
    cudaGetSymbolAddress((void**)&cB,     g_cB);
    cudaGetSymbolAddress((void**)&dis,    g_dis);
    cudaGetSymbolAddress((void**)&cnt,    g_cnt);
    cudaGetSymbolAddress((void**)&fill,   g_fill);
    cudaGetSymbolAddress((void**)&rowptr, g_rowptr);
    cudaGetSymbolAddress((void**)&csr,    g_csr);
    cudaGetSymbolAddress((void**)&bsum,   g_bsum);

    const int mt = (NN + 127) / 128;
    const int nb = (NN + 255) / 256;
    const int ne = (E + 255) / 256;

    // ---- MLP first (also: puts sgemm_bias at the ncu -s 5 capture slot) ----
    sgemm_bias<<<dim3(HID / 128, mt), 256>>>(x,  W_in,  b_in,  h1, NN, INC, HID);
    sgemm_bias<<<dim3(HID / 128, mt), 256>>>(h1, W1,    b1,    h2, NN, HID, HID);
    ln_relu_kernel<<<(NN * 32 + 255) / 256, 256>>>(h2, g1, be1, NN);
    sgemm_bias<<<dim3(HID / 128, mt), 256>>>(h2, W2,    b2,    h1, NN, HID, HID);
    ln_relu_kernel<<<(NN * 32 + 255) / 256, 256>>>(h1, g2, be2, NN);
    sgemm_bias<<<dim3(OUTC / 128, mt), 256>>>(h1, W_out, b_out, h0, NN, HID, OUTC);

    // ---- graph prep (independent of MLP; recomputed every call) ----
    zero_kernel<<<nb, 256>>>(cnt, fill);
    deg_count_kernel<<<ne, 256>>>(dst, cnt, E);
    dis_kernel<<<nb, 256>>>(cnt, dis);
    scan_partial<<<nb, 256>>>(cnt, rowptr, bsum);
    scan_bsums<<<1, 512>>>(bsum, nb);
    add_offsets<<<nb, 256>>>(rowptr, bsum, E);
    fill_kernel<<<ne, 256>>>(src, dst, dis, rowptr, fill, csr, E);

    // fp16 copy of h0 = initial carry and teleport source for steps 0..8
    const int cvt_blocks = (NN * 32 + 255) / 256;
    f2h_kernel<<<cvt_blocks, 256>>>(h0, h016);

    // ---- APPNP: 10 fused pull steps, fp16 carry (2 nodes/warp), fp32 final ----
    const __half* carry = h016;
    const int warps = (NN + 1) / 2;
    const int step_blocks = (warps * 32 + 255) / 256;
    for (int t = 0; t < KSTEPS; t++) {
        int is_last = (t == KSTEPS - 1);
        __half* o16 = (t & 1) ? cB : cA;
        appnp_step_kernel<<<step_blocks, 256>>>(rowptr, csr, dis, h0, h016,
                                                carry, o16, out, is_last);
        carry = o16;
    }
}

// round 12
// speedup vs baseline: 1.2854x; 1.0340x over previous
#include <cuda_runtime.h>
#include <cuda_fp16.h>

#define NN      100000
#define INC     512
#define HID     256
#define OUTC    128
#define EMAX    1600000
#define KSTEPS  10
#define ALPHA_F 0.1f
#define ONEMA_F 0.9f
#define LNEPS   1e-5f

// ---------------- static device scratch (no allocation allowed) ----------------
__device__ float  g_h1[(size_t)NN * HID];
__device__ float  g_h2[(size_t)NN * HID];
__device__ float  g_h0[(size_t)NN * OUTC];      // fp32 teleport source
__device__ __half g_h016[(size_t)NN * OUTC];    // fp16 copy of h0
__device__ __half g_cA[(size_t)NN * OUTC];      // fp16 carry ping
__device__ __half g_cB[(size_t)NN * OUTC];      // fp16 carry pong
__device__ float  g_dis[NN];
__device__ int    g_cnt[NN];
__device__ int    g_fill[NN];
__device__ int    g_rowptr[NN + 1];
__device__ int2   g_csr[EMAX];                  // packed {src, weight-bits}
__device__ int    g_bsum[512];

// ---------------- fp32 SGEMM with packed f32x2 FMA (FFMA2) ---------------------
// 128x128 tile, 256 threads, 8x8 micro-tile, K-tile 8.
// Inner loop uses fma.rn.f32x2: 32 FFMA2 + 8 mov.b64 per kk instead of 64 FFMA.
__global__ void __launch_bounds__(256, 2)
sgemm_bias(const float* __restrict__ A, const float* __restrict__ B,
           const float* __restrict__ bias, float* __restrict__ C,
           int M, int K, int N)
{
    __shared__ float sA[8][128];
    __shared__ float sB[8][128];

    const int tid = threadIdx.x;
    const int bm  = blockIdx.y * 128;
    const int bn  = blockIdx.x * 128;
    const int tx  = tid & 15;
    const int ty  = tid >> 4;

    const int a_row = tid >> 1;
    const int a_k4  = (tid & 1) * 4;
    const bool m_ok = (bm + a_row) < M;
    const int b_k = tid >> 5;
    const int b_n = (tid & 31) * 4;

    const float* a_ptr = A + (size_t)(bm + a_row) * K + a_k4;
    const float* b_ptr = B + (size_t)b_k * N + (bn + b_n);

    // packed accumulators: accp[i][j2] = (acc[i][2*j2], acc[i][2*j2+1])
    unsigned long long accp[8][4];
    #pragma unroll
    for (int i = 0; i < 8; i++)
        #pragma unroll
        for (int j = 0; j < 4; j++)
            accp[i][j] = 0ull;

    float4 avr = m_ok ? *(const float4*)a_ptr : make_float4(0.f, 0.f, 0.f, 0.f);
    float4 bvr = *(const float4*)b_ptr;

    const int nt = K / 8;
    for (int t = 0; t < nt; t++) {
        sA[a_k4 + 0][a_row] = avr.x;
        sA[a_k4 + 1][a_row] = avr.y;
        sA[a_k4 + 2][a_row] = avr.z;
        sA[a_k4 + 3][a_row] = avr.w;
        *(float4*)&sB[b_k][b_n] = bvr;
        __syncthreads();

        if (t + 1 < nt) {
            avr = m_ok ? *(const float4*)(a_ptr + (t + 1) * 8)
                       : make_float4(0.f, 0.f, 0.f, 0.f);
            bvr = *(const float4*)(b_ptr + (size_t)(t + 1) * 8 * N);
        }

        #pragma unroll
        for (int kk = 0; kk < 8; kk++) {
            float4 a0 = *(const float4*)&sA[kk][ty * 8];
            float4 a1 = *(const float4*)&sA[kk][ty * 8 + 4];
            float4 b0 = *(const float4*)&sB[kk][tx * 8];
            float4 b1 = *(const float4*)&sB[kk][tx * 8 + 4];

            unsigned long long bp0, bp1, bp2, bp3;
            asm("mov.b64 %0, {%1, %2};" : "=l"(bp0) : "f"(b0.x), "f"(b0.y));
            asm("mov.b64 %0, {%1, %2};" : "=l"(bp1) : "f"(b0.z), "f"(b0.w));
            asm("mov.b64 %0, {%1, %2};" : "=l"(bp2) : "f"(b1.x), "f"(b1.y));
            asm("mov.b64 %0, {%1, %2};" : "=l"(bp3) : "f"(b1.z), "f"(b1.w));

            float a[8] = {a0.x, a0.y, a0.z, a0.w, a1.x, a1.y, a1.z, a1.w};
            #pragma unroll
            for (int i = 0; i < 8; i++) {
                unsigned long long ap;
                asm("mov.b64 %0, {%1, %1};" : "=l"(ap) : "f"(a[i]));
                asm("fma.rn.f32x2 %0, %1, %2, %0;" : "+l"(accp[i][0]) : "l"(ap), "l"(bp0));
                asm("fma.rn.f32x2 %0, %1, %2, %0;" : "+l"(accp[i][1]) : "l"(ap), "l"(bp1));
                asm("fma.rn.f32x2 %0, %1, %2, %0;" : "+l"(accp[i][2]) : "l"(ap), "l"(bp2));
                asm("fma.rn.f32x2 %0, %1, %2, %0;" : "+l"(accp[i][3]) : "l"(ap), "l"(bp3));
            }
        }
        __syncthreads();
    }

    #pragma unroll
    for (int i = 0; i < 8; i++) {
        int m = bm + ty * 8 + i;
        if (m < M) {
            #pragma unroll
            for (int j2 = 0; j2 < 4; j2++) {
                int n = bn + tx * 8 + j2 * 2;
                float lo, hi;
                asm("mov.b64 {%0, %1}, %2;" : "=f"(lo), "=f"(hi) : "l"(accp[i][j2]));
                C[(size_t)m * N + n]     = lo + bias[n];
                C[(size_t)m * N + n + 1] = hi + bias[n + 1];
            }
        }
    }
}

// ---------------- fused LayerNorm + ReLU (warp per row of 256) ------------------
__global__ void ln_relu_kernel(float* __restrict__ h, const float* __restrict__ g,
                               const float* __restrict__ be, int M)
{
    int warp = (blockIdx.x * blockDim.x + threadIdx.x) >> 5;
    if (warp >= M) return;
    int lane = threadIdx.x & 31;

    float4* row = (float4*)(h + (size_t)warp * HID);
    float4 v0 = row[lane];
    float4 v1 = row[lane + 32];

    float s  = v0.x + v0.y + v0.z + v0.w + v1.x + v1.y + v1.z + v1.w;
    float sq = v0.x * v0.x + v0.y * v0.y + v0.z * v0.z + v0.w * v0.w
             + v1.x * v1.x + v1.y * v1.y + v1.z * v1.z + v1.w * v1.w;
    #pragma unroll
    for (int o = 16; o > 0; o >>= 1) {
        s  += __shfl_xor_sync(0xffffffffu, s, o);
        sq += __shfl_xor_sync(0xffffffffu, sq, o);
    }
    float mu   = s * (1.0f / 256.0f);
    float var  = sq * (1.0f / 256.0f) - mu * mu;
    float rstd = rsqrtf(var + LNEPS);

    const float4* g4 = (const float4*)g;
    const float4* b4 = (const float4*)be;
    float4 G0 = g4[lane], G1 = g4[lane + 32];
    float4 B0 = b4[lane], B1 = b4[lane + 32];

    v0.x = fmaxf((v0.x - mu) * rstd * G0.x + B0.x, 0.f);
    v0.y = fmaxf((v0.y - mu) * rstd * G0.y + B0.y, 0.f);
    v0.z = fmaxf((v0.z - mu) * rstd * G0.z + B0.z, 0.f);
    v0.w = fmaxf((v0.w - mu) * rstd * G0.w + B0.w, 0.f);
    v1.x = fmaxf((v1.x - mu) * rstd * G1.x + B1.x, 0.f);
    v1.y = fmaxf((v1.y - mu) * rstd * G1.y + B1.y, 0.f);
    v1.z = fmaxf((v1.z - mu) * rstd * G1.z + B1.z, 0.f);
    v1.w = fmaxf((v1.w - mu) * rstd * G1.w + B1.w, 0.f);

    row[lane]      = v0;
    row[lane + 32] = v1;
}

// ---------------- graph prep: CSR by dst ---------------------------------------
__global__ void zero_kernel(int* __restrict__ cnt, int* __restrict__ fill)
{
    int i = blockIdx.x * blockDim.x + threadIdx.x;
    if (i < NN) { cnt[i] = 0; fill[i] = 0; }
}

__global__ void deg_count_kernel(const int* __restrict__ dst, int* __restrict__ cnt, int E)
{
    int e = blockIdx.x * blockDim.x + threadIdx.x;
    if (e < E) atomicAdd(&cnt[dst[e]], 1);
}

__global__ void dis_kernel(const int* __restrict__ cnt, float* __restrict__ dis)
{
    int i = blockIdx.x * blockDim.x + threadIdx.x;
    if (i < NN) dis[i] = rsqrtf((float)(cnt[i] + 1));
}

__global__ void scan_partial(const int* __restrict__ cnt, int* __restrict__ rowptr,
                             int* __restrict__ bsum)
{
    __shared__ int s[256];
    int tid = threadIdx.x;
    int i = blockIdx.x * 256 + tid;
    int v = (i < NN) ? cnt[i] : 0;
    s[tid] = v;
    __syncthreads();
    #pragma unroll
    for (int o = 1; o < 256; o <<= 1) {
        int t = 0;
        if (tid >= o) t = s[tid - o];
        __syncthreads();
        if (tid >= o) s[tid] += t;
        __syncthreads();
    }
    if (i < NN) rowptr[i] = s[tid] - v;
    if (tid == 255) bsum[blockIdx.x] = s[255];
}

__global__ void scan_bsums(int* __restrict__ bsum, int nb)
{
    __shared__ int s[512];
    int tid = threadIdx.x;
    int v = (tid < nb) ? bsum[tid] : 0;
    s[tid] = v;
    __syncthreads();
    #pragma unroll
    for (int o = 1; o < 512; o <<= 1) {
        int t = 0;
        if (tid >= o) t = s[tid - o];
        __syncthreads();
        if (tid >= o) s[tid] += t;
        __syncthreads();
    }
    if (tid < nb) bsum[tid] = s[tid] - v;
}

__global__ void add_offsets(int* __restrict__ rowptr, const int* __restrict__ bsum, int E)
{
    int i = blockIdx.x * blockDim.x + threadIdx.x;
    if (i < NN) rowptr[i] += bsum[i >> 8];
    if (i == 0) rowptr[NN] = E;
}

__global__ void fill_kernel(const int* __restrict__ src, const int* __restrict__ dst,
                            const float* __restrict__ dis,
                            const int* __restrict__ rowptr, int* __restrict__ fill,
                            int2* __restrict__ csr, int E)
{
    int e = blockIdx.x * blockDim.x + threadIdx.x;
    if (e >= E) return;
    int si = src[e];
    int di = dst[e];
    int p = rowptr[di] + atomicAdd(&fill[di], 1);
    float w = ONEMA_F * dis[si] * dis[di];
    csr[p] = make_int2(si, __float_as_int(w));
}

// ---------------- fp32 -> fp16 convert (4 elems / thread) ----------------------
__global__ void f2h_kernel(const float* __restrict__ in, __half* __restrict__ out)
{
    int idx = blockIdx.x * blockDim.x + threadIdx.x;   // over NN*32 float4s
    if (idx >= NN * (OUTC / 4)) return;
    float4 v = ((const float4*)in)[idx];
    __half2 lo = __floats2half2_rn(v.x, v.y);
    __half2 hi = __floats2half2_rn(v.z, v.w);
    uint2 o;
    o.x = *(unsigned*)&lo;
    o.y = *(unsigned*)&hi;
    ((uint2*)out)[idx] = o;
}

// ---------------- APPNP step: 2 nodes per warp (16 lanes each), uint4 gathers ---
// out[i] = alpha*h0[i] + (1-alpha)/deg[i]*carry[i] + sum_e w_e*carry[src_e]
__global__ void __launch_bounds__(256)
appnp_step_kernel(const int* __restrict__ rowptr,
                  const int2* __restrict__ csr,
                  const float* __restrict__ dis,
                  const float* __restrict__ h0f,
                  const __half* __restrict__ h016,
                  const __half* __restrict__ carry,
                  __half* __restrict__ out16,
                  float* __restrict__ outf,
                  int last)
{
    int warp_id = (blockIdx.x * blockDim.x + threadIdx.x) >> 5;
    int lane = threadIdx.x & 31;
    int node = warp_id * 2 + (lane >> 4);
    int l16  = lane & 15;
    if (node >= NN) return;

    const uint4* c = (const uint4*)carry;   // 16 uint4 per node row (256 B)
    int beg = rowptr[node];
    int end = rowptr[node + 1];
    float ds = dis[node];
    float wself = ONEMA_F * ds * ds;

    uint4 cv = c[node * 16 + l16];
    float2 s0 = __half22float2(*(__half2*)&cv.x);
    float2 s1 = __half22float2(*(__half2*)&cv.y);
    float2 s2 = __half22float2(*(__half2*)&cv.z);
    float2 s3 = __half22float2(*(__half2*)&cv.w);
    float acc[8];
    acc[0] = wself * s0.x; acc[1] = wself * s0.y;
    acc[2] = wself * s1.x; acc[3] = wself * s1.y;
    acc[4] = wself * s2.x; acc[5] = wself * s2.y;
    acc[6] = wself * s3.x; acc[7] = wself * s3.y;

    int e = beg;
    // 4-way unroll: 4 gathers in flight per 16-lane group (~1KB/warp outstanding)
    for (; e + 3 < end; e += 4) {
        int2 c0 = __ldg(&csr[e]);
        int2 c1 = __ldg(&csr[e + 1]);
        int2 c2 = __ldg(&csr[e + 2]);
        int2 c3 = __ldg(&csr[e + 3]);
        uint4 p0 = c[c0.x * 16 + l16];
        uint4 p1 = c[c1.x * 16 + l16];
        uint4 p2 = c[c2.x * 16 + l16];
        uint4 p3 = c[c3.x * 16 + l16];
        float w0 = __int_as_float(c0.y);
        float w1 = __int_as_float(c1.y);
        float w2 = __int_as_float(c2.y);
        float w3 = __int_as_float(c3.y);
        {
            float2 a0 = __half22float2(*(__half2*)&p0.x);
            float2 a1 = __half22float2(*(__half2*)&p0.y);
            float2 a2 = __half22float2(*(__half2*)&p0.z);
            float2 a3 = __half22float2(*(__half2*)&p0.w);
            acc[0] = fmaf(w0, a0.x, acc[0]); acc[1] = fmaf(w0, a0.y, acc[1]);
            acc[2] = fmaf(w0, a1.x, acc[2]); acc[3] = fmaf(w0, a1.y, acc[3]);
            acc[4] = fmaf(w0, a2.x, acc[4]); acc[5] = fmaf(w0, a2.y, acc[5]);
            acc[6] = fmaf(w0, a3.x, acc[6]); acc[7] = fmaf(w0, a3.y, acc[7]);
        }
        {
            float2 a0 = __half22float2(*(__half2*)&p1.x);
            float2 a1 = __half22float2(*(__half2*)&p1.y);
            float2 a2 = __half22float2(*(__half2*)&p1.z);
            float2 a3 = __half22float2(*(__half2*)&p1.w);
            acc[0] = fmaf(w1, a0.x, acc[0]); acc[1] = fmaf(w1, a0.y, acc[1]);
            acc[2] = fmaf(w1, a1.x, acc[2]); acc[3] = fmaf(w1, a1.y, acc[3]);
            acc[4] = fmaf(w1, a2.x, acc[4]); acc[5] = fmaf(w1, a2.y, acc[5]);
            acc[6] = fmaf(w1, a3.x, acc[6]); acc[7] = fmaf(w1, a3.y, acc[7]);
        }
        {
            float2 a0 = __half22float2(*(__half2*)&p2.x);
            float2 a1 = __half22float2(*(__half2*)&p2.y);
            float2 a2 = __half22float2(*(__half2*)&p2.z);
            float2 a3 = __half22float2(*(__half2*)&p2.w);
            acc[0] = fmaf(w2, a0.x, acc[0]); acc[1] = fmaf(w2, a0.y, acc[1]);
            acc[2] = fmaf(w2, a1.x, acc[2]); acc[3] = fmaf(w2, a1.y, acc[3]);
            acc[4] = fmaf(w2, a2.x, acc[4]); acc[5] = fmaf(w2, a2.y, acc[5]);
            acc[6] = fmaf(w2, a3.x, acc[6]); acc[7] = fmaf(w2, a3.y, acc[7]);
        }
        {
            float2 a0 = __half22float2(*(__half2*)&p3.x);
            float2 a1 = __half22float2(*(__half2*)&p3.y);
            float2 a2 = __half22float2(*(__half2*)&p3.z);
            float2 a3 = __half22float2(*(__half2*)&p3.w);
            acc[0] = fmaf(w3, a0.x, acc[0]); acc[1] = fmaf(w3, a0.y, acc[1]);
            acc[2] = fmaf(w3, a1.x, acc[2]); acc[3] = fmaf(w3, a1.y, acc[3]);
            acc[4] = fmaf(w3, a2.x, acc[4]); acc[5] = fmaf(w3, a2.y, acc[5]);
            acc[6] = fmaf(w3, a3.x, acc[6]); acc[7] = fmaf(w3, a3.y, acc[7]);
        }
    }
    for (; e < end; e++) {
        int2 c0 = __ldg(&csr[e]);
        uint4 p0 = c[c0.x * 16 + l16];
        float w0 = __int_as_float(c0.y);
        float2 a0 = __half22float2(*(__half2*)&p0.x);
        float2 a1 = __half22float2(*(__half2*)&p0.y);
        float2 a2 = __half22float2(*(__half2*)&p0.z);
        float2 a3 = __half22float2(*(__half2*)&p0.w);
        acc[0] = fmaf(w0, a0.x, acc[0]); acc[1] = fmaf(w0, a0.y, acc[1]);
        acc[2] = fmaf(w0, a1.x, acc[2]); acc[3] = fmaf(w0, a1.y, acc[3]);
        acc[4] = fmaf(w0, a2.x, acc[4]); acc[5] = fmaf(w0, a2.y, acc[5]);
        acc[6] = fmaf(w0, a3.x, acc[6]); acc[7] = fmaf(w0, a3.y, acc[7]);
    }

    if (last) {
        const float4* h4 = (const float4*)h0f + node * 32 + l16 * 2;
        float4 ha = __ldcs(h4);
        float4 hb = __ldcs(h4 + 1);
        float4 oa, ob;
        oa.x = fmaf(ALPHA_F, ha.x, acc[0]);
        oa.y = fmaf(ALPHA_F, ha.y, acc[1]);
        oa.z = fmaf(ALPHA_F, ha.z, acc[2]);
        oa.w = fmaf(ALPHA_F, ha.w, acc[3]);
        ob.x = fmaf(ALPHA_F, hb.x, acc[4]);
        ob.y = fmaf(ALPHA_F, hb.y, acc[5]);
        ob.z = fmaf(ALPHA_F, hb.z, acc[6]);
        ob.w = fmaf(ALPHA_F, hb.w, acc[7]);
        float4* o4 = (float4*)outf + node * 32 + l16 * 2;
        __stcs(o4, oa);
        __stcs(o4 + 1, ob);
    } else {
        uint4 hp = ((const uint4*)h016)[node * 16 + l16];
        float2 h0v = __half22float2(*(__half2*)&hp.x);
        float2 h1v = __half22float2(*(__half2*)&hp.y);
        float2 h2v = __half22float2(*(__half2*)&hp.z);
        float2 h3v = __half22float2(*(__half2*)&hp.w);
        __half2 q0 = __floats2half2_rn(fmaf(ALPHA_F, h0v.x, acc[0]),
                                       fmaf(ALPHA_F, h0v.y, acc[1]));
        __half2 q1 = __floats2half2_rn(fmaf(ALPHA_F, h1v.x, acc[2]),
                                       fmaf(ALPHA_F, h1v.y, acc[3]));
        __half2 q2 = __floats2half2_rn(fmaf(ALPHA_F, h2v.x, acc[4]),
                                       fmaf(ALPHA_F, h2v.y, acc[5]));
        __half2 q3 = __floats2half2_rn(fmaf(ALPHA_F, h3v.x, acc[6]),
                                       fmaf(ALPHA_F, h3v.y, acc[7]));
        uint4 ov;
        ov.x = *(unsigned*)&q0;
        ov.y = *(unsigned*)&q1;
        ov.z = *(unsigned*)&q2;
        ov.w = *(unsigned*)&q3;
        ((uint4*)out16)[node * 16 + l16] = ov;
    }
}

// ---------------- launch --------------------------------------------------------
extern "C" void kernel_launch(void* const* d_in, const int* in_sizes, int n_in,
                              void* d_out, int out_size)
{
    const float* x     = (const float*)d_in[0];
    const int*   ei    = (const int*)  d_in[1];
    const float* W_in  = (const float*)d_in[2];
    const float* b_in  = (const float*)d_in[3];
    const float* W1    = (const float*)d_in[4];
    const float* b1    = (const float*)d_in[5];
    const float* g1    = (const float*)d_in[6];
    const float* be1   = (const float*)d_in[7];
    const float* W2    = (const float*)d_in[8];
    const float* b2    = (const float*)d_in[9];
    const float* g2    = (const float*)d_in[10];
    const float* be2   = (const float*)d_in[11];
    const float* W_out = (const float*)d_in[12];
    const float* b_out = (const float*)d_in[13];
    float* out = (float*)d_out;

    int E = in_sizes[1] / 2;
    if (E > EMAX) E = EMAX;
    const int* src = ei;
    const int* dst = ei + E;

    float *h1, *h2, *h0, *dis;
    __half *h016, *cA, *cB;
    int *cnt, *fill, *rowptr, *bsum;
    int2 *csr;
    cudaGetSymbolAddress((void**)&h1,     g_h1);
    cudaGetSymbolAddress((void**)&h2,     g_h2);
    cudaGetSymbolAddress((void**)&h0,     g_h0);
    cudaGetSymbolAddress((void**)&h016,   g_h016);
    cudaGetSymbolAddress((void**)&cA,     g_cA);
    cudaGetSymbolAddress((void**)&cB,     g_cB);
    cudaGetSymbolAddress((void**)&dis,    g_dis);
    cudaGetSymbolAddress((void**)&cnt,    g_cnt);
    cudaGetSymbolAddress((void**)&fill,   g_fill);
    cudaGetSymbolAddress((void**)&rowptr, g_rowptr);
    cudaGetSymbolAddress((void**)&csr,    g_csr);
    cudaGetSymbolAddress((void**)&bsum,   g_bsum);

    const int mt = (NN + 127) / 128;
    const int nb = (NN + 255) / 256;
    const int ne = (E + 255) / 256;

    // ---- MLP first (keeps sgemm_bias at the ncu capture slot) ----
    sgemm_bias<<<dim3(HID / 128, mt), 256>>>(x,  W_in,  b_in,  h1, NN, INC, HID);
    sgemm_bias<<<dim3(HID / 128, mt), 256>>>(h1, W1,    b1,    h2, NN, HID, HID);
    ln_relu_kernel<<<(NN * 32 + 255) / 256, 256>>>(h2, g1, be1, NN);
    sgemm_bias<<<dim3(HID / 128, mt), 256>>>(h2, W2,    b2,    h1, NN, HID, HID);
    ln_relu_kernel<<<(NN * 32 + 255) / 256, 256>>>(h1, g2, be2, NN);
    sgemm_bias<<<dim3(OUTC / 128, mt), 256>>>(h1, W_out, b_out, h0, NN, HID, OUTC);

    // ---- graph prep (independent of MLP; recomputed every call) ----
    zero_kernel<<<nb, 256>>>(cnt, fill);
    deg_count_kernel<<<ne, 256>>>(dst, cnt, E);
    dis_kernel<<<nb, 256>>>(cnt, dis);
    scan_partial<<<nb, 256>>>(cnt, rowptr, bsum);
    scan_bsums<<<1, 512>>>(bsum, nb);
    add_offsets<<<nb, 256>>>(rowptr, bsum, E);
    fill_kernel<<<ne, 256>>>(src, dst, dis, rowptr, fill, csr, E);

    // fp16 copy of h0 = initial carry and teleport source for steps 0..8
    const int cvt_blocks = (NN * 32 + 255) / 256;
    f2h_kernel<<<cvt_blocks, 256>>>(h0, h016);

    // ---- APPNP: 10 fused pull steps, fp16 carry (2 nodes/warp), fp32 final ----
    const __half* carry = h016;
    const int warps = (NN + 1) / 2;
    const int step_blocks = (warps * 32 + 255) / 256;
    for (int t = 0; t < KSTEPS; t++) {
        int is_last = (t == KSTEPS - 1);
        __half* o16 = (t & 1) ? cB : cA;
        appnp_step_kernel<<<step_blocks, 256>>>(rowptr, csr, dis, h0, h016,
                                                carry, o16, out, is_last);
        carry = o16;
    }
}

// round 14
// speedup vs baseline: 1.7721x; 1.3786x over previous
#include <cuda_runtime.h>
#include <cuda_fp16.h>
#include <cuda_bf16.h>
#include <mma.h>

using namespace nvcuda;

#define NN      100000
#define INC     512
#define HID     256
#define OUTC    128
#define EMAX    1600000
#define KSTEPS  10
#define ALPHA_F 0.1f
#define ONEMA_F 0.9f
#define LNEPS   1e-5f

// ---------------- static device scratch (no allocation allowed) ----------------
__device__ float  g_h1[(size_t)NN * HID];
__device__ float  g_h2[(size_t)NN * HID];
__device__ float  g_h0[(size_t)NN * OUTC];      // fp32 teleport source
__device__ __half g_h016[(size_t)NN * OUTC];    // fp16 copy of h0
__device__ __half g_cA[(size_t)NN * OUTC];      // fp16 carry ping
__device__ __half g_cB[(size_t)NN * OUTC];      // fp16 carry pong
__device__ float  g_dis[NN];
__device__ int    g_cnt[NN];
__device__ int    g_fill[NN];
__device__ int    g_rowptr[NN + 1];
__device__ int2   g_csr[EMAX];                  // packed {src, weight-bits}
__device__ int    g_bsum[512];

// ---------------- split-bf16 tensor-core GEMM ----------------------------------
// C[M,N] = A[M,K]@B[K,N] + bias, fp32 in/out.
// A,B split into bf16 hi/lo per k-chunk; C = Ah*Bh + Ah*Bl + Al*Bh (fp32 accum).
// 128x128 block tile, 256 threads = 8 warps in 2(m) x 4(n); warp tile 64x32.
#define LDA 40     // bf16 elems; 80 B row stride (mult of 16 B, conflict-free)
#define LDB 136    // bf16 elems; 272 B row stride (mult of 16 B, conflict-free)

__global__ void __launch_bounds__(256, 2)
wgemm_bias(const float* __restrict__ A, const float* __restrict__ B,
           const float* __restrict__ bias, float* __restrict__ C,
           int M, int K, int N)
{
    __shared__ __nv_bfloat16 sAh[128 * LDA];
    __shared__ __nv_bfloat16 sAl[128 * LDA];
    __shared__ __nv_bfloat16 sBh[16 * LDB];
    __shared__ __nv_bfloat16 sBl[16 * LDB];
    __shared__ float         sCb[16 * 128];    // replicated bias tile

    const int tid = threadIdx.x;
    const int bm  = blockIdx.y * 128;
    const int bn  = blockIdx.x * 128;
    const int wid = tid >> 5;
    const int wm  = wid >> 2;        // 0..1
    const int wn  = wid & 3;         // 0..3

    // bias tile: row r, col c -> bias[bn + c]
    for (int i = tid; i < 16 * 128; i += 256)
        sCb[i] = bias[bn + (i & 127)];
    __syncthreads();

    wmma::fragment<wmma::accumulator, 16, 16, 16, float> cf[4][2];
    #pragma unroll
    for (int mf = 0; mf < 4; mf++)
        #pragma unroll
        for (int nf = 0; nf < 2; nf++)
            wmma::load_matrix_sync(cf[mf][nf], sCb + wn * 32 + nf * 16, 128,
                                   wmma::mem_row_major);

    // staging index maps
    const int a_row = tid >> 1;              // 0..127
    const int a_c4  = (tid & 1) * 8;         // 0 or 8 (two float4 = 8 floats)
    const int b_row = tid >> 4;              // 0..15
    const int b_c4  = (tid & 15) * 8;        // 0..120

    for (int k0 = 0; k0 < K; k0 += 16) {
        __syncthreads();
        // ---- stage A chunk: 128 x 16 fp32 -> hi/lo bf16 ----
        {
            int gm = bm + a_row;
            const float* ap = A + (size_t)gm * K + k0 + a_c4;
            float4 v0, v1;
            if (gm < M) { v0 = *(const float4*)ap; v1 = *(const float4*)(ap + 4); }
            else        { v0 = make_float4(0,0,0,0); v1 = v0; }
            float va[8] = {v0.x, v0.y, v0.z, v0.w, v1.x, v1.y, v1.z, v1.w};
            #pragma unroll
            for (int i = 0; i < 8; i++) {
                __nv_bfloat16 h = __float2bfloat16_rn(va[i]);
                __nv_bfloat16 l = __float2bfloat16_rn(va[i] - __bfloat162float(h));
                sAh[a_row * LDA + a_c4 + i] = h;
                sAl[a_row * LDA + a_c4 + i] = l;
            }
        }
        // ---- stage B chunk: 16 x 128 fp32 -> hi/lo bf16 ----
        {
            const float* bp = B + (size_t)(k0 + b_row) * N + bn + b_c4;
            float4 v0 = *(const float4*)bp;
            float4 v1 = *(const float4*)(bp + 4);
            float vb[8] = {v0.x, v0.y, v0.z, v0.w, v1.x, v1.y, v1.z, v1.w};
            #pragma unroll
            for (int i = 0; i < 8; i++) {
                __nv_bfloat16 h = __float2bfloat16_rn(vb[i]);
                __nv_bfloat16 l = __float2bfloat16_rn(vb[i] - __bfloat162float(h));
                sBh[b_row * LDB + b_c4 + i] = h;
                sBl[b_row * LDB + b_c4 + i] = l;
            }
        }
        __syncthreads();

        // ---- warp-level mma: acc += Ah*Bh + Ah*Bl + Al*Bh ----
        wmma::fragment<wmma::matrix_a, 16, 16, 16, __nv_bfloat16, wmma::row_major> af[4];
        wmma::fragment<wmma::matrix_b, 16, 16, 16, __nv_bfloat16, wmma::row_major> bh[2], bl[2];

        #pragma unroll
        for (int nf = 0; nf < 2; nf++) {
            wmma::load_matrix_sync(bh[nf], sBh + wn * 32 + nf * 16, LDB);
            wmma::load_matrix_sync(bl[nf], sBl + wn * 32 + nf * 16, LDB);
        }
        #pragma unroll
        for (int mf = 0; mf < 4; mf++)
            wmma::load_matrix_sync(af[mf], sAh + (wm * 64 + mf * 16) * LDA, LDA);
        #pragma unroll
        for (int mf = 0; mf < 4; mf++)
            #pragma unroll
            for (int nf = 0; nf < 2; nf++) {
                wmma::mma_sync(cf[mf][nf], af[mf], bh[nf], cf[mf][nf]);
                wmma::mma_sync(cf[mf][nf], af[mf], bl[nf], cf[mf][nf]);
            }
        #pragma unroll
        for (int mf = 0; mf < 4; mf++)
            wmma::load_matrix_sync(af[mf], sAl + (wm * 64 + mf * 16) * LDA, LDA);
        #pragma unroll
        for (int mf = 0; mf < 4; mf++)
            #pragma unroll
            for (int nf = 0; nf < 2; nf++)
                wmma::mma_sync(cf[mf][nf], af[mf], bh[nf], cf[mf][nf]);
    }

    // ---- epilogue: M % 16 == 0, so frag-granular guard is exact ----
    #pragma unroll
    for (int mf = 0; mf < 4; mf++) {
        int m = bm + wm * 64 + mf * 16;
        if (m < M) {
            #pragma unroll
            for (int nf = 0; nf < 2; nf++)
                wmma::store_matrix_sync(C + (size_t)m * N + bn + wn * 32 + nf * 16,
                                        cf[mf][nf], N, wmma::mem_row_major);
        }
    }
}

// ---------------- fused LayerNorm + ReLU (warp per row of 256) ------------------
__global__ void ln_relu_kernel(float* __restrict__ h, const float* __restrict__ g,
                               const float* __restrict__ be, int M)
{
    int warp = (blockIdx.x * blockDim.x + threadIdx.x) >> 5;
    if (warp >= M) return;
    int lane = threadIdx.x & 31;

    float4* row = (float4*)(h + (size_t)warp * HID);
    float4 v0 = row[lane];
    float4 v1 = row[lane + 32];

    float s  = v0.x + v0.y + v0.z + v0.w + v1.x + v1.y + v1.z + v1.w;
    float sq = v0.x * v0.x + v0.y * v0.y + v0.z * v0.z + v0.w * v0.w
             + v1.x * v1.x + v1.y * v1.y + v1.z * v1.z + v1.w * v1.w;
    #pragma unroll
    for (int o = 16; o > 0; o >>= 1) {
        s  += __shfl_xor_sync(0xffffffffu, s, o);
        sq += __shfl_xor_sync(0xffffffffu, sq, o);
    }
    float mu   = s * (1.0f / 256.0f);
    float var  = sq * (1.0f / 256.0f) - mu * mu;
    float rstd = rsqrtf(var + LNEPS);

    const float4* g4 = (const float4*)g;
    const float4* b4 = (const float4*)be;
    float4 G0 = g4[lane], G1 = g4[lane + 32];
    float4 B0 = b4[lane], B1 = b4[lane + 32];

    v0.x = fmaxf((v0.x - mu) * rstd * G0.x + B0.x, 0.f);
    v0.y = fmaxf((v0.y - mu) * rstd * G0.y + B0.y, 0.f);
    v0.z = fmaxf((v0.z - mu) * rstd * G0.z + B0.z, 0.f);
    v0.w = fmaxf((v0.w - mu) * rstd * G0.w + B0.w, 0.f);
    v1.x = fmaxf((v1.x - mu) * rstd * G1.x + B1.x, 0.f);
    v1.y = fmaxf((v1.y - mu) * rstd * G1.y + B1.y, 0.f);
    v1.z = fmaxf((v1.z - mu) * rstd * G1.z + B1.z, 0.f);
    v1.w = fmaxf((v1.w - mu) * rstd * G1.w + B1.w, 0.f);

    row[lane]      = v0;
    row[lane + 32] = v1;
}

// ---------------- graph prep: CSR by dst ---------------------------------------
__global__ void zero_kernel(int* __restrict__ cnt, int* __restrict__ fill)
{
    int i = blockIdx.x * blockDim.x + threadIdx.x;
    if (i < NN) { cnt[i] = 0; fill[i] = 0; }
}

__global__ void deg_count_kernel(const int* __restrict__ dst, int* __restrict__ cnt, int E)
{
    int e = blockIdx.x * blockDim.x + threadIdx.x;
    if (e < E) atomicAdd(&cnt[dst[e]], 1);
}

__global__ void dis_kernel(const int* __restrict__ cnt, float* __restrict__ dis)
{
    int i = blockIdx.x * blockDim.x + threadIdx.x;
    if (i < NN) dis[i] = rsqrtf((float)(cnt[i] + 1));
}

__global__ void scan_partial(const int* __restrict__ cnt, int* __restrict__ rowptr,
                             int* __restrict__ bsum)
{
    __shared__ int s[256];
    int tid = threadIdx.x;
    int i = blockIdx.x * 256 + tid;
    int v = (i < NN) ? cnt[i] : 0;
    s[tid] = v;
    __syncthreads();
    #pragma unroll
    for (int o = 1; o < 256; o <<= 1) {
        int t = 0;
        if (tid >= o) t = s[tid - o];
        __syncthreads();
        if (tid >= o) s[tid] += t;
        __syncthreads();
    }
    if (i < NN) rowptr[i] = s[tid] - v;
    if (tid == 255) bsum[blockIdx.x] = s[255];
}

__global__ void scan_bsums(int* __restrict__ bsum, int nb)
{
    __shared__ int s[512];
    int tid = threadIdx.x;
    int v = (tid < nb) ? bsum[tid] : 0;
    s[tid] = v;
    __syncthreads();
    #pragma unroll
    for (int o = 1; o < 512; o <<= 1) {
        int t = 0;
        if (tid >= o) t = s[tid - o];
        __syncthreads();
        if (tid >= o) s[tid] += t;
        __syncthreads();
    }
    if (tid < nb) bsum[tid] = s[tid] - v;
}

__global__ void add_offsets(int* __restrict__ rowptr, const int* __restrict__ bsum, int E)
{
    int i = blockIdx.x * blockDim.x + threadIdx.x;
    if (i < NN) rowptr[i] += bsum[i >> 8];
    if (i == 0) rowptr[NN] = E;
}

__global__ void fill_kernel(const int* __restrict__ src, const int* __restrict__ dst,
                            const float* __restrict__ dis,
                            const int* __restrict__ rowptr, int* __restrict__ fill,
                            int2* __restrict__ csr, int E)
{
    int e = blockIdx.x * blockDim.x + threadIdx.x;
    if (e >= E) return;
    int si = src[e];
    int di = dst[e];
    int p = rowptr[di] + atomicAdd(&fill[di], 1);
    float w = ONEMA_F * dis[si] * dis[di];
    csr[p] = make_int2(si, __float_as_int(w));
}

// ---------------- fp32 -> fp16 convert (4 elems / thread) ----------------------
__global__ void f2h_kernel(const float* __restrict__ in, __half* __restrict__ out)
{
    int idx = blockIdx.x * blockDim.x + threadIdx.x;   // over NN*32 float4s
    if (idx >= NN * (OUTC / 4)) return;
    float4 v = ((const float4*)in)[idx];
    __half2 lo = __floats2half2_rn(v.x, v.y);
    __half2 hi = __floats2half2_rn(v.z, v.w);
    uint2 o;
    o.x = *(unsigned*)&lo;
    o.y = *(unsigned*)&hi;
    ((uint2*)out)[idx] = o;
}

// ---------------- APPNP step: 2 nodes per warp (16 lanes each), uint4 gathers ---
__global__ void __launch_bounds__(256)
appnp_step_kernel(const int* __restrict__ rowptr,
                  const int2* __restrict__ csr,
                  const float* __restrict__ dis,
                  const float* __restrict__ h0f,
                  const __half* __restrict__ h016,
                  const __half* __restrict__ carry,
                  __half* __restrict__ out16,
                  float* __restrict__ outf,
                  int last)
{
    int warp_id = (blockIdx.x * blockDim.x + threadIdx.x) >> 5;
    int lane = threadIdx.x & 31;
    int node = warp_id * 2 + (lane >> 4);
    int l16  = lane & 15;
    if (node >= NN) return;

    const uint4* c = (const uint4*)carry;
    int beg = rowptr[node];
    int end = rowptr[node + 1];
    float ds = dis[node];
    float wself = ONEMA_F * ds * ds;

    uint4 cv = c[node * 16 + l16];
    float2 s0 = __half22float2(*(__half2*)&cv.x);
    float2 s1 = __half22float2(*(__half2*)&cv.y);
    float2 s2 = __half22float2(*(__half2*)&cv.z);
    float2 s3 = __half22float2(*(__half2*)&cv.w);
    float acc[8];
    acc[0] = wself * s0.x; acc[1] = wself * s0.y;
    acc[2] = wself * s1.x; acc[3] = wself * s1.y;
    acc[4] = wself * s2.x; acc[5] = wself * s2.y;
    acc[6] = wself * s3.x; acc[7] = wself * s3.y;

    int e = beg;
    for (; e + 3 < end; e += 4) {
        int2 c0 = __ldg(&csr[e]);
        int2 c1 = __ldg(&csr[e + 1]);
        int2 c2 = __ldg(&csr[e + 2]);
        int2 c3 = __ldg(&csr[e + 3]);
        uint4 p0 = c[c0.x * 16 + l16];
        uint4 p1 = c[c1.x * 16 + l16];
        uint4 p2 = c[c2.x * 16 + l16];
        uint4 p3 = c[c3.x * 16 + l16];
        float w0 = __int_as_float(c0.y);
        float w1 = __int_as_float(c1.y);
        float w2 = __int_as_float(c2.y);
        float w3 = __int_as_float(c3.y);
        {
            float2 a0 = __half22float2(*(__half2*)&p0.x);
            float2 a1 = __half22float2(*(__half2*)&p0.y);
            float2 a2 = __half22float2(*(__half2*)&p0.z);
            float2 a3 = __half22float2(*(__half2*)&p0.w);
            acc[0] = fmaf(w0, a0.x, acc[0]); acc[1] = fmaf(w0, a0.y, acc[1]);
            acc[2] = fmaf(w0, a1.x, acc[2]); acc[3] = fmaf(w0, a1.y, acc[3]);
            acc[4] = fmaf(w0, a2.x, acc[4]); acc[5] = fmaf(w0, a2.y, acc[5]);
            acc[6] = fmaf(w0, a3.x, acc[6]); acc[7] = fmaf(w0, a3.y, acc[7]);
        }
        {
            float2 a0 = __half22float2(*(__half2*)&p1.x);
            float2 a1 = __half22float2(*(__half2*)&p1.y);
            float2 a2 = __half22float2(*(__half2*)&p1.z);
            float2 a3 = __half22float2(*(__half2*)&p1.w);
            acc[0] = fmaf(w1, a0.x, acc[0]); acc[1] = fmaf(w1, a0.y, acc[1]);
            acc[2] = fmaf(w1, a1.x, acc[2]); acc[3] = fmaf(w1, a1.y, acc[3]);
            acc[4] = fmaf(w1, a2.x, acc[4]); acc[5] = fmaf(w1, a2.y, acc[5]);
            acc[6] = fmaf(w1, a3.x, acc[6]); acc[7] = fmaf(w1, a3.y, acc[7]);
        }
        {
            float2 a0 = __half22float2(*(__half2*)&p2.x);
            float2 a1 = __half22float2(*(__half2*)&p2.y);
            float2 a2 = __half22float2(*(__half2*)&p2.z);
            float2 a3 = __half22float2(*(__half2*)&p2.w);
            acc[0] = fmaf(w2, a0.x, acc[0]); acc[1] = fmaf(w2, a0.y, acc[1]);
            acc[2] = fmaf(w2, a1.x, acc[2]); acc[3] = fmaf(w2, a1.y, acc[3]);
            acc[4] = fmaf(w2, a2.x, acc[4]); acc[5] = fmaf(w2, a2.y, acc[5]);
            acc[6] = fmaf(w2, a3.x, acc[6]); acc[7] = fmaf(w2, a3.y, acc[7]);
        }
        {
            float2 a0 = __half22float2(*(__half2*)&p3.x);
            float2 a1 = __half22float2(*(__half2*)&p3.y);
            float2 a2 = __half22float2(*(__half2*)&p3.z);
            float2 a3 = __half22float2(*(__half2*)&p3.w);
            acc[0] = fmaf(w3, a0.x, acc[0]); acc[1] = fmaf(w3, a0.y, acc[1]);
            acc[2] = fmaf(w3, a1.x, acc[2]); acc[3] = fmaf(w3, a1.y, acc[3]);
            acc[4] = fmaf(w3, a2.x, acc[4]); acc[5] = fmaf(w3, a2.y, acc[5]);
            acc[6] = fmaf(w3, a3.x, acc[6]); acc[7] = fmaf(w3, a3.y, acc[7]);
        }
    }
    for (; e < end; e++) {
        int2 c0 = __ldg(&csr[e]);
        uint4 p0 = c[c0.x * 16 + l16];
        float w0 = __int_as_float(c0.y);
        float2 a0 = __half22float2(*(__half2*)&p0.x);
        float2 a1 = __half22float2(*(__half2*)&p0.y);
        float2 a2 = __half22float2(*(__half2*)&p0.z);
        float2 a3 = __half22float2(*(__half2*)&p0.w);
        acc[0] = fmaf(w0, a0.x, acc[0]); acc[1] = fmaf(w0, a0.y, acc[1]);
        acc[2] = fmaf(w0, a1.x, acc[2]); acc[3] = fmaf(w0, a1.y, acc[3]);
        acc[4] = fmaf(w0, a2.x, acc[4]); acc[5] = fmaf(w0, a2.y, acc[5]);
        acc[6] = fmaf(w0, a3.x, acc[6]); acc[7] = fmaf(w0, a3.y, acc[7]);
    }

    if (last) {
        const float4* h4 = (const float4*)h0f + node * 32 + l16 * 2;
        float4 ha = __ldcs(h4);
        float4 hb = __ldcs(h4 + 1);
        float4 oa, ob;
        oa.x = fmaf(ALPHA_F, ha.x, acc[0]);
        oa.y = fmaf(ALPHA_F, ha.y, acc[1]);
        oa.z = fmaf(ALPHA_F, ha.z, acc[2]);
        oa.w = fmaf(ALPHA_F, ha.w, acc[3]);
        ob.x = fmaf(ALPHA_F, hb.x, acc[4]);
        ob.y = fmaf(ALPHA_F, hb.y, acc[5]);
        ob.z = fmaf(ALPHA_F, hb.z, acc[6]);
        ob.w = fmaf(ALPHA_F, hb.w, acc[7]);
        float4* o4 = (float4*)outf + node * 32 + l16 * 2;
        __stcs(o4, oa);
        __stcs(o4 + 1, ob);
    } else {
        uint4 hp = ((const uint4*)h016)[node * 16 + l16];
        float2 h0v = __half22float2(*(__half2*)&hp.x);
        float2 h1v = __half22float2(*(__half2*)&hp.y);
        float2 h2v = __half22float2(*(__half2*)&hp.z);
        float2 h3v = __half22float2(*(__half2*)&hp.w);
        __half2 q0 = __floats2half2_rn(fmaf(ALPHA_F, h0v.x, acc[0]),
                                       fmaf(ALPHA_F, h0v.y, acc[1]));
        __half2 q1 = __floats2half2_rn(fmaf(ALPHA_F, h1v.x, acc[2]),
                                       fmaf(ALPHA_F, h1v.y, acc[3]));
        __half2 q2 = __floats2half2_rn(fmaf(ALPHA_F, h2v.x, acc[4]),
                                       fmaf(ALPHA_F, h2v.y, acc[5]));
        __half2 q3 = __floats2half2_rn(fmaf(ALPHA_F, h3v.x, acc[6]),
                                       fmaf(ALPHA_F, h3v.y, acc[7]));
        uint4 ov;
        ov.x = *(unsigned*)&q0;
        ov.y = *(unsigned*)&q1;
        ov.z = *(unsigned*)&q2;
        ov.w = *(unsigned*)&q3;
        ((uint4*)out16)[node * 16 + l16] = ov;
    }
}

// ---------------- launch --------------------------------------------------------
extern "C" void kernel_launch(void* const* d_in, const int* in_sizes, int n_in,
                              void* d_out, int out_size)
{
    const float* x     = (const float*)d_in[0];
    const int*   ei    = (const int*)  d_in[1];
    const float* W_in  = (const float*)d_in[2];
    const float* b_in  = (const float*)d_in[3];
    const float* W1    = (const float*)d_in[4];
    const float* b1    = (const float*)d_in[5];
    const float* g1    = (const float*)d_in[6];
    const float* be1   = (const float*)d_in[7];
    const float* W2    = (const float*)d_in[8];
    const float* b2    = (const float*)d_in[9];
    const float* g2    = (const float*)d_in[10];
    const float* be2   = (const float*)d_in[11];
    const float* W_out = (const float*)d_in[12];
    const float* b_out = (const float*)d_in[13];
    float* out = (float*)d_out;

    int E = in_sizes[1] / 2;
    if (E > EMAX) E = EMAX;
    const int* src = ei;
    const int* dst = ei + E;

    float *h1, *h2, *h0, *dis;
    __half *h016, *cA, *cB;
    int *cnt, *fill, *rowptr, *bsum;
    int2 *csr;
    cudaGetSymbolAddress((void**)&h1,     g_h1);
    cudaGetSymbolAddress((void**)&h2,     g_h2);
    cudaGetSymbolAddress((void**)&h0,     g_h0);
    cudaGetSymbolAddress((void**)&h016,   g_h016);
    cudaGetSymbolAddress((void**)&cA,     g_cA);
    cudaGetSymbolAddress((void**)&cB,     g_cB);
    cudaGetSymbolAddress((void**)&dis,    g_dis);
    cudaGetSymbolAddress((void**)&cnt,    g_cnt);
    cudaGetSymbolAddress((void**)&fill,   g_fill);
    cudaGetSymbolAddress((void**)&rowptr, g_rowptr);
    cudaGetSymbolAddress((void**)&csr,    g_csr);
    cudaGetSymbolAddress((void**)&bsum,   g_bsum);

    const int mt = (NN + 127) / 128;
    const int nb = (NN + 255) / 256;
    const int ne = (E + 255) / 256;

    // ---- MLP: split-bf16 tensor-core GEMMs ----
    wgemm_bias<<<dim3(HID / 128, mt), 256>>>(x,  W_in,  b_in,  h1, NN, INC, HID);
    wgemm_bias<<<dim3(HID / 128, mt), 256>>>(h1, W1,    b1,    h2, NN, HID, HID);
    ln_relu_kernel<<<(NN * 32 + 255) / 256, 256>>>(h2, g1, be1, NN);
    wgemm_bias<<<dim3(HID / 128, mt), 256>>>(h2, W2,    b2,    h1, NN, HID, HID);
    ln_relu_kernel<<<(NN * 32 + 255) / 256, 256>>>(h1, g2, be2, NN);
    wgemm_bias<<<dim3(OUTC / 128, mt), 256>>>(h1, W_out, b_out, h0, NN, HID, OUTC);

    // ---- graph prep (independent of MLP; recomputed every call) ----
    zero_kernel<<<nb, 256>>>(cnt, fill);
    deg_count_kernel<<<ne, 256>>>(dst, cnt, E);
    dis_kernel<<<nb, 256>>>(cnt, dis);
    scan_partial<<<nb, 256>>>(cnt, rowptr, bsum);
    scan_bsums<<<1, 512>>>(bsum, nb);
    add_offsets<<<nb, 256>>>(rowptr, bsum, E);
    fill_kernel<<<ne, 256>>>(src, dst, dis, rowptr, fill, csr, E);

    // fp16 copy of h0 = initial carry and teleport source for steps 0..8
    const int cvt_blocks = (NN * 32 + 255) / 256;
    f2h_kernel<<<cvt_blocks, 256>>>(h0, h016);

    // ---- APPNP: 10 fused pull steps, fp16 carry (2 nodes/warp), fp32 final ----
    const __half* carry = h016;
    const int warps = (NN + 1) / 2;
    const int step_blocks = (warps * 32 + 255) / 256;
    for (int t = 0; t < KSTEPS; t++) {
        int is_last = (t == KSTEPS - 1);
        __half* o16 = (t & 1) ? cB : cA;
        appnp_step_kernel<<<step_blocks, 256>>>(rowptr, csr, dis, h0, h016,
                                                carry, o16, out, is_last);
        carry = o16;
    }
}